// round 6
// baseline (speedup 1.0000x reference)
#include <cuda_runtime.h>
#include <cuda_bf16.h>
#include <math.h>
#include <stdint.h>

// Problem constants
#define BB   8
#define CC   512
#define LL   4096
#define HH   8
#define TK   256
#define MM   2048
#define CHD  64
#define BLROWS (BB*LL)   // 32768

// ---------------- scratch (device globals; no allocation allowed) ----------
__device__ __align__(16) float g_xt  [(size_t)BB*LL*CC];
__device__ __align__(16) float g_q   [(size_t)BB*LL*CC];
__device__ __align__(16) float g_kv  [(size_t)BB*LL*2*CC];
__device__ __align__(16) float g_kn  [(size_t)BB*LL*CC];
__device__ __align__(16) float g_vt  [(size_t)BB*LL*CC];
__device__ __align__(16) float g_pp  [(size_t)BB*32*CC];
__device__ __align__(16) float g_probe[BB*CC];
__device__ __align__(16) float g_score[BB*HH*LL];
__device__ __align__(16) int   g_idx [BB*HH*TK];
__device__ __align__(16) float g_kp  [(size_t)BB*TK*CC];
__device__ __align__(16) float g_vp  [(size_t)BB*TK*CC];
__device__ __align__(16) float g_qp  [(size_t)BB*LL*CC];
__device__ __align__(16) float g_a   [(size_t)BB*LL*CC];
__device__ __align__(16) float g_h2  [(size_t)BB*LL*CC];
__device__ __align__(16) float g_h1  [(size_t)BB*LL*MM];

// bf16 hi/lo split activations
__device__ __align__(16) __nv_bfloat16 g_xt_h[(size_t)BB*LL*CC];
__device__ __align__(16) __nv_bfloat16 g_xt_l[(size_t)BB*LL*CC];
__device__ __align__(16) __nv_bfloat16 g_q_h [(size_t)BB*LL*CC];
__device__ __align__(16) __nv_bfloat16 g_q_l [(size_t)BB*LL*CC];
__device__ __align__(16) __nv_bfloat16 g_kc_h[(size_t)BB*TK*CC];
__device__ __align__(16) __nv_bfloat16 g_kc_l[(size_t)BB*TK*CC];
__device__ __align__(16) __nv_bfloat16 g_vc_h[(size_t)BB*TK*CC];
__device__ __align__(16) __nv_bfloat16 g_vc_l[(size_t)BB*TK*CC];
__device__ __align__(16) __nv_bfloat16 g_ao_h[(size_t)BB*LL*CC];
__device__ __align__(16) __nv_bfloat16 g_ao_l[(size_t)BB*LL*CC];
__device__ __align__(16) __nv_bfloat16 g_a_h [(size_t)BB*LL*CC];
__device__ __align__(16) __nv_bfloat16 g_a_l [(size_t)BB*LL*CC];
__device__ __align__(16) __nv_bfloat16 g_h1_h[(size_t)BB*LL*MM];
__device__ __align__(16) __nv_bfloat16 g_h1_l[(size_t)BB*LL*MM];

// bf16 hi/lo weights
__device__ __align__(16) __nv_bfloat16 g_wq_h [CC*CC],    g_wq_l [CC*CC];
__device__ __align__(16) __nv_bfloat16 g_wkv_h[2*CC*CC],  g_wkv_l[2*CC*CC];
__device__ __align__(16) __nv_bfloat16 g_win_h[3*CC*CC],  g_win_l[3*CC*CC];
__device__ __align__(16) __nv_bfloat16 g_wo_h [CC*CC],    g_wo_l [CC*CC];
__device__ __align__(16) __nv_bfloat16 g_w1_h [MM*CC],    g_w1_l [MM*CC];
__device__ __align__(16) __nv_bfloat16 g_w2_h [CC*MM],    g_w2_l [CC*MM];

// ================= helpers ===================================================
static __device__ __forceinline__ uint32_t smem_u32(const void* p) {
    uint32_t a;
    asm("{ .reg .u64 t; cvta.to.shared.u64 t, %1; cvt.u32.u64 %0, t; }"
        : "=r"(a) : "l"(p));
    return a;
}
static __device__ __forceinline__ void split_bf16(float v, __nv_bfloat16& h, __nv_bfloat16& l) {
    h = __float2bfloat16(v);
    l = __float2bfloat16(v - __bfloat162float(h));
}
static __device__ __forceinline__ void ldmA(uint32_t* r, uint32_t addr) {
    asm volatile("ldmatrix.sync.aligned.m8n8.x4.shared.b16 {%0,%1,%2,%3}, [%4];"
                 : "=r"(r[0]), "=r"(r[1]), "=r"(r[2]), "=r"(r[3]) : "r"(addr));
}
static __device__ __forceinline__ void ldmB(uint32_t* r, uint32_t addr) {
    asm volatile("ldmatrix.sync.aligned.m8n8.x2.shared.b16 {%0,%1}, [%2];"
                 : "=r"(r[0]), "=r"(r[1]) : "r"(addr));
}
static __device__ __forceinline__ void mma16816(float* d, const uint32_t* a, const uint32_t* b) {
    asm volatile(
        "mma.sync.aligned.m16n8k16.row.col.f32.bf16.bf16.f32 "
        "{%0,%1,%2,%3}, {%4,%5,%6,%7}, {%8,%9}, {%0,%1,%2,%3};"
        : "+f"(d[0]), "+f"(d[1]), "+f"(d[2]), "+f"(d[3])
        : "r"(a[0]), "r"(a[1]), "r"(a[2]), "r"(a[3]), "r"(b[0]), "r"(b[1]));
}
static __device__ __forceinline__ void cpasync16(uint32_t saddr, const void* gaddr) {
    asm volatile("cp.async.cg.shared.global [%0], [%1], 16;"
                 :: "r"(saddr), "l"(gaddr) : "memory");
}

// ================= tensor-core GEMM via mma.sync ============================
// Y(row,col) = sum_K Xhi/lo(row,K) * Whi/lo(col,K) + bias[col]
// CTA tile 128x256, BK=32, 512 threads = 16 warps (4M x 4N), warp tile 32x64.
// bf16 3-product split: D += Ah*Bh + Ah*Bl + Al*Bh.
// smem per stage: Ah(128x80) Al(128x80) Bh(256x80) Bl(256x80) = 61440B; 3 stages.
#define AH_OFF 0
#define AL_OFF 10240
#define BH_OFF 20480
#define BL_OFF 40960
#define STG    61440
__global__ void __launch_bounds__(512, 1) k_gemm_mma(
    const __nv_bfloat16* __restrict__ Ah, const __nv_bfloat16* __restrict__ Al,
    const __nv_bfloat16* __restrict__ Bh, const __nv_bfloat16* __restrict__ Bl,
    const float* __restrict__ bias, float* __restrict__ Y, int N, int K)
{
    extern __shared__ __align__(128) char smem[];
    const uint32_t sb = smem_u32(smem);
    const int tid  = threadIdx.x;
    const int wid  = tid >> 5, lane = tid & 31;
    const int wm   = wid & 3;              // warp M 0..3 (32 rows)
    const int wn   = wid >> 2;             // warp N 0..3 (64 cols)
    const int bm = blockIdx.y << 7, bn = blockIdx.x << 8;

    const int nch = K >> 5;                // chunks of BK=32

    float acc[2][8][4];
    #pragma unroll
    for (int m = 0; m < 2; m++)
        #pragma unroll
        for (int n = 0; n < 8; n++)
            #pragma unroll
            for (int v = 0; v < 4; v++) acc[m][n][v] = 0.f;

    // ---- async load of one chunk into stage s (512 thr x 6 units of 16B) ----
    auto load_chunk = [&](int ck, int s) {
        const int k0 = ck << 5;
        const uint32_t so = sb + s * STG;
        #pragma unroll
        for (int i = 0; i < 6; i++) {
            const int idx = tid + (i << 9);   // 0..3071 16B units
            const __nv_bfloat16* src;
            int local; uint32_t dst; int rb;
            if (i < 1)      { src = Ah; local = idx;        dst = AH_OFF; rb = bm; }
            else if (i < 2) { src = Al; local = idx - 512;  dst = AL_OFF; rb = bm; }
            else if (i < 4) { src = Bh; local = idx - 1024; dst = BH_OFF; rb = bn; }
            else            { src = Bl; local = idx - 2048; dst = BL_OFF; rb = bn; }
            const int row = local >> 2, seg = local & 3;
            cpasync16(so + dst + row * 80 + (seg << 4),
                      src + (size_t)(rb + row) * K + k0 + (seg << 3));
        }
        asm volatile("cp.async.commit_group;" ::: "memory");
    };

    load_chunk(0, 0);
    load_chunk(1, 1);

    // ldmatrix lane offsets
    const uint32_t aRow = (lane & 7) + ((lane >> 3) & 1) * 8;
    const uint32_t aKof = (lane >> 4) * 8;
    const uint32_t bRow = (lane & 7);
    const uint32_t bKof = ((lane >> 3) & 1) * 8;

    for (int ck = 0; ck < nch; ck++) {
        if (ck + 2 < nch) {
            load_chunk(ck + 2, (ck + 2) % 3);
            asm volatile("cp.async.wait_group 2;" ::: "memory");
        } else if (ck + 1 < nch) {
            asm volatile("cp.async.wait_group 1;" ::: "memory");
        } else {
            asm volatile("cp.async.wait_group 0;" ::: "memory");
        }
        __syncthreads();

        const uint32_t so = sb + (ck % 3) * STG;
        #pragma unroll
        for (int ks = 0; ks < 2; ks++) {
            uint32_t ah[2][4], al[2][4];
            #pragma unroll
            for (int mf = 0; mf < 2; mf++) {
                uint32_t row = wm * 32 + mf * 16 + aRow;
                uint32_t off = row * 80 + (aKof + ks * 16) * 2;
                ldmA(ah[mf], so + AH_OFF + off);
                ldmA(al[mf], so + AL_OFF + off);
            }
            #pragma unroll
            for (int nt = 0; nt < 8; nt++) {
                uint32_t row = wn * 64 + nt * 8 + bRow;
                uint32_t off = row * 80 + (bKof + ks * 16) * 2;
                uint32_t bh[2], bl[2];
                ldmB(bh, so + BH_OFF + off);
                ldmB(bl, so + BL_OFF + off);
                #pragma unroll
                for (int mf = 0; mf < 2; mf++) {
                    mma16816(acc[mf][nt], ah[mf], bh);
                    mma16816(acc[mf][nt], ah[mf], bl);
                    mma16816(acc[mf][nt], al[mf], bh);
                }
            }
        }
        __syncthreads();
    }

    // ---- epilogue: bias add, direct fp32 stores ----
    const int r  = lane >> 2;
    const int c2 = (lane & 3) << 1;
    #pragma unroll
    for (int mf = 0; mf < 2; mf++) {
        const int gm = bm + wm * 32 + mf * 16;
        #pragma unroll
        for (int nt = 0; nt < 8; nt++) {
            const int gn = bn + wn * 64 + nt * 8 + c2;
            float bx = bias[gn], by = bias[gn + 1];
            float2 v0 = make_float2(acc[mf][nt][0] + bx, acc[mf][nt][1] + by);
            float2 v1 = make_float2(acc[mf][nt][2] + bx, acc[mf][nt][3] + by);
            *(float2*)(Y + (size_t)(gm + r) * N + gn)     = v0;
            *(float2*)(Y + (size_t)(gm + r + 8) * N + gn) = v1;
        }
    }
}

// ---------------- weight fp32 -> bf16 hi/lo ---------------------------------
__global__ void k_cvt(const float* __restrict__ x, __nv_bfloat16* __restrict__ h,
                      __nv_bfloat16* __restrict__ l, int n) {
    int i = (blockIdx.x * 256 + threadIdx.x) * 4;
    if (i >= n) return;
    float4 v = *(const float4*)(x + i);
    __nv_bfloat16 hh, ll;
    split_bf16(v.x, hh, ll); h[i+0] = hh; l[i+0] = ll;
    split_bf16(v.y, hh, ll); h[i+1] = hh; l[i+1] = ll;
    split_bf16(v.z, hh, ll); h[i+2] = hh; l[i+2] = ll;
    split_bf16(v.w, hh, ll); h[i+3] = hh; l[i+3] = ll;
}

// ---------------- transpose (B,C,L) -> (B,L,C), fp32 + bf16 hi/lo ----------
__global__ void k_transpose_in(const float* __restrict__ X, float* __restrict__ Y,
                               __nv_bfloat16* __restrict__ YH, __nv_bfloat16* __restrict__ YL) {
    __shared__ float tile[32][33];
    int b  = blockIdx.z;
    int l0 = blockIdx.x << 5, c0 = blockIdx.y << 5;
    int tx = threadIdx.x, ty = threadIdx.y;
    const float* Xb = X + (size_t)b*CC*LL;
    #pragma unroll
    for (int i = ty; i < 32; i += 8)
        tile[i][tx] = Xb[(size_t)(c0+i)*LL + l0 + tx];
    __syncthreads();
    size_t base = (size_t)b*LL*CC;
    #pragma unroll
    for (int i = ty; i < 32; i += 8) {
        float v = tile[tx][i];
        size_t o = base + (size_t)(l0+i)*CC + c0 + tx;
        Y[o] = v;
        __nv_bfloat16 hh, ll; split_bf16(v, hh, ll);
        YH[o] = hh; YL[o] = ll;
    }
}

// ---------------- out = transpose(H + A), (B,L,C) -> (B,C,L) ---------------
__global__ void k_add_transpose_out(const float* __restrict__ Hh, const float* __restrict__ A,
                                    float* __restrict__ OUT) {
    __shared__ float tile[32][33];
    int b  = blockIdx.z;
    int l0 = blockIdx.x << 5, c0 = blockIdx.y << 5;
    int tx = threadIdx.x, ty = threadIdx.y;
    const float* Hb = Hh + (size_t)b*LL*CC;
    const float* Ab = A  + (size_t)b*LL*CC;
    #pragma unroll
    for (int i = ty; i < 32; i += 8) {
        size_t o = (size_t)(l0+i)*CC + c0 + tx;
        tile[i][tx] = Hb[o] + Ab[o];
    }
    __syncthreads();
    float* Ob = OUT + (size_t)b*CC*LL;
    #pragma unroll
    for (int i = ty; i < 32; i += 8)
        Ob[(size_t)(c0+i)*LL + l0 + tx] = tile[tx][i];
}

// ---------------- warp-per-row LayerNorm, Wd=512, fused epilogues -----------
// mode 0: plain LN ; 1: LN + per-64-chunk l2n ; 2: LN*gamma + resid ; 3: relu
__global__ void k_ln512(const float* __restrict__ in, int ld_in,
                        float* __restrict__ out,
                        const float* __restrict__ gam, const float* __restrict__ bet,
                        int mode, const float* __restrict__ gamma_p,
                        const float* __restrict__ resid,
                        __nv_bfloat16* __restrict__ oh, __nv_bfloat16* __restrict__ ol) {
    const int lane = threadIdx.x & 31;
    const int row  = blockIdx.x * 8 + (threadIdx.x >> 5);
    const float* xr = in + (size_t)row * ld_in + lane * 16;

    float v[16];
    float s = 0.f, s2 = 0.f;
    #pragma unroll
    for (int j = 0; j < 16; j += 4) {
        float4 t = *(const float4*)(xr + j);
        v[j]=t.x; v[j+1]=t.y; v[j+2]=t.z; v[j+3]=t.w;
        s += t.x+t.y+t.z+t.w;
        s2 += t.x*t.x+t.y*t.y+t.z*t.z+t.w*t.w;
    }
    #pragma unroll
    for (int o = 16; o > 0; o >>= 1) {
        s  += __shfl_xor_sync(0xffffffffu, s,  o);
        s2 += __shfl_xor_sync(0xffffffffu, s2, o);
    }
    const float mu = s * (1.f/512.f);
    const float rstd = rsqrtf(s2 * (1.f/512.f) - mu*mu + 1e-5f);

    float y[16];
    const int cb = lane * 16;
    #pragma unroll
    for (int i = 0; i < 16; i++)
        y[i] = (v[i] - mu) * rstd * gam[cb + i] + bet[cb + i];

    if (mode == 1) {           // l2n over 64-ch chunk = 4 adjacent lanes
        float qq = 0.f;
        #pragma unroll
        for (int i = 0; i < 16; i++) qq += y[i]*y[i];
        qq += __shfl_xor_sync(0xffffffffu, qq, 1);
        qq += __shfl_xor_sync(0xffffffffu, qq, 2);
        float sc = 1.f / fmaxf(sqrtf(qq), 1e-12f);
        #pragma unroll
        for (int i = 0; i < 16; i++) y[i] *= sc;
    } else if (mode == 2) {
        float gsc = gamma_p[0];
        const float* rr = resid + (size_t)row * 512 + cb;
        #pragma unroll
        for (int i = 0; i < 16; i++) y[i] = y[i]*gsc + rr[i];
    } else if (mode == 3) {
        #pragma unroll
        for (int i = 0; i < 16; i++) y[i] = fmaxf(y[i], 0.f);
    }
    size_t ob = (size_t)row * 512 + cb;
    if (out) {
        #pragma unroll
        for (int j = 0; j < 16; j += 4)
            *(float4*)(out + ob + j) = make_float4(y[j], y[j+1], y[j+2], y[j+3]);
    }
    if (oh) {
        #pragma unroll
        for (int i = 0; i < 16; i++) {
            __nv_bfloat16 hh, ll; split_bf16(y[i], hh, ll);
            oh[ob + i] = hh; ol[ob + i] = ll;
        }
    }
}

// ---------------- warp-per-row LN+relu, Wd=2048, bf16 hi/lo out only --------
__global__ void k_ln2048(const float* __restrict__ in,
                         const float* __restrict__ gam, const float* __restrict__ bet,
                         __nv_bfloat16* __restrict__ oh, __nv_bfloat16* __restrict__ ol) {
    const int lane = threadIdx.x & 31;
    const int row  = blockIdx.x * 8 + (threadIdx.x >> 5);
    const float* xr = in + (size_t)row * 2048;

    float s = 0.f, s2 = 0.f;
    #pragma unroll
    for (int w = 0; w < 16; w++) {
        float4 t = *(const float4*)(xr + ((w*32 + lane) << 2));
        s  += t.x+t.y+t.z+t.w;
        s2 += t.x*t.x+t.y*t.y+t.z*t.z+t.w*t.w;
    }
    #pragma unroll
    for (int o = 16; o > 0; o >>= 1) {
        s  += __shfl_xor_sync(0xffffffffu, s,  o);
        s2 += __shfl_xor_sync(0xffffffffu, s2, o);
    }
    const float mu = s * (1.f/2048.f);
    const float rstd = rsqrtf(s2 * (1.f/2048.f) - mu*mu + 1e-5f);

    #pragma unroll
    for (int w = 0; w < 16; w++) {
        const int e = (w*32 + lane) << 2;
        float4 t = *(const float4*)(xr + e);
        float4 g = *(const float4*)(gam + e);
        float4 bb = *(const float4*)(bet + e);
        float y0 = fmaxf((t.x-mu)*rstd*g.x + bb.x, 0.f);
        float y1 = fmaxf((t.y-mu)*rstd*g.y + bb.y, 0.f);
        float y2 = fmaxf((t.z-mu)*rstd*g.z + bb.z, 0.f);
        float y3 = fmaxf((t.w-mu)*rstd*g.w + bb.w, 0.f);
        size_t ob = (size_t)row * 2048 + e;
        __nv_bfloat16 hh, ll;
        split_bf16(y0, hh, ll); oh[ob+0]=hh; ol[ob+0]=ll;
        split_bf16(y1, hh, ll); oh[ob+1]=hh; ol[ob+1]=ll;
        split_bf16(y2, hh, ll); oh[ob+2]=hh; ol[ob+2]=ll;
        split_bf16(y3, hh, ll); oh[ob+3]=hh; ol[ob+3]=ll;
    }
}

// ---------------- q_probe = sum over L of QN --------------------------------
__global__ void k_probe_partial(const float* __restrict__ QN, float* __restrict__ part) {
    int b = blockIdx.x, ch = blockIdx.y;
    int c = threadIdx.x;
    const int CHUNK = LL / 32;
    const float* p = QN + ((size_t)b*LL + (size_t)ch*CHUNK)*CC + c;
    float s = 0.f;
    for (int i = 0; i < CHUNK; i++) s += p[(size_t)i*CC];
    part[((size_t)b*32 + ch)*CC + c] = s;
}
__global__ void k_probe_reduce(const float* __restrict__ part, float* __restrict__ probe) {
    int b = blockIdx.x; int c = threadIdx.x;
    float s = 0.f;
    for (int ch = 0; ch < 32; ch++) s += part[((size_t)b*32 + ch)*CC + c];
    probe[b*CC + c] = s;
}

// ---------------- score[b,h,l] = probe . (|k|+k) -----------------------------
__global__ void k_score(const float* __restrict__ KN, const float* __restrict__ probe,
                        float* __restrict__ score) {
    int gw   = (blockIdx.x * blockDim.x + threadIdx.x) >> 5;
    int lane = threadIdx.x & 31;
    if (gw >= BB*LL) return;
    int b = gw >> 12;
    int l = gw & (LL-1);
    const float* krow = KN + (size_t)gw*CC;
    const float* pr   = probe + b*CC;
    int c0 = lane << 4;
    float s = 0.f;
    #pragma unroll
    for (int j = 0; j < 16; j += 4) {
        float4 k4 = *(const float4*)(krow + c0 + j);
        float4 p4 = *(const float4*)(pr   + c0 + j);
        s += p4.x*(fabsf(k4.x)+k4.x) + p4.y*(fabsf(k4.y)+k4.y)
           + p4.z*(fabsf(k4.z)+k4.z) + p4.w*(fabsf(k4.w)+k4.w);
    }
    s += __shfl_xor_sync(0xffffffffu, s, 1);
    s += __shfl_xor_sync(0xffffffffu, s, 2);
    if ((lane & 3) == 0) {
        int h = lane >> 2;
        score[((size_t)(b*HH + h))*LL + l] = s;
    }
}

// ---------------- exact top-k via in-smem bitonic sort -----------------------
__global__ void k_topk(const float* __restrict__ score, int* __restrict__ idx) {
    __shared__ unsigned long long keys[LL];
    int bh = blockIdx.x;
    const float* s = score + (size_t)bh*LL;
    for (int i = threadIdx.x; i < LL; i += blockDim.x) {
        unsigned u = __float_as_uint(s[i]);
        u = (u & 0x80000000u) ? ~u : (u | 0x80000000u);
        keys[i] = ((unsigned long long)u << 32) | (unsigned)(LL-1-i);
    }
    __syncthreads();
    for (int k = 2; k <= LL; k <<= 1) {
        for (int j = k >> 1; j > 0; j >>= 1) {
            for (int i = threadIdx.x; i < LL; i += blockDim.x) {
                int ixj = i ^ j;
                if (ixj > i) {
                    unsigned long long a = keys[i], c = keys[ixj];
                    bool desc = (i & k) == 0;
                    if (desc ? (a < c) : (a > c)) { keys[i] = c; keys[ixj] = a; }
                }
            }
            __syncthreads();
        }
    }
    for (int t = threadIdx.x; t < TK; t += blockDim.x)
        idx[bh*TK + t] = (LL-1) - (int)(unsigned)(keys[t] & 0xffffffffu);
}

// ---------------- gather selected K/V rows per head -> bf16 hi/lo ------------
__global__ void k_gather(const float* __restrict__ KN, const float* __restrict__ VT,
                         const int* __restrict__ idx,
                         __nv_bfloat16* __restrict__ KCH, __nv_bfloat16* __restrict__ KCL,
                         __nv_bfloat16* __restrict__ VCH, __nv_bfloat16* __restrict__ VCL) {
    int bt = blockIdx.x;
    int b = bt / TK, t = bt % TK;
    int c = threadIdx.x;
    int h = c >> 6;
    int l = idx[(b*HH + h)*TK + t];
    size_t src = ((size_t)b*LL + l)*CC + c;
    size_t dst = (size_t)bt*CC + c;
    __nv_bfloat16 hh, ll;
    split_bf16(KN[src], hh, ll); KCH[dst] = hh; KCL[dst] = ll;
    split_bf16(VT[src], hh, ll); VCH[dst] = hh; VCL[dst] = ll;
}

// ---------------- attention: per (b,h,64-query tile), online softmax ---------
__global__ void k_attn(const float* __restrict__ QP, const float* __restrict__ KP,
                       const float* __restrict__ VP, const float* __restrict__ bk,
                       const float* __restrict__ bv,
                       __nv_bfloat16* __restrict__ AOH, __nv_bfloat16* __restrict__ AOL) {
    __shared__ float Ks[64][64];
    __shared__ float Vs[64][64];
    int bh = blockIdx.y;
    int b = bh >> 3, h = bh & 7;
    int l0 = blockIdx.x << 6;
    int tid = threadIdx.x;
    int g = tid >> 2;
    int r = tid & 3;
    int l = l0 + g;
    const int cbase = h*CHD + r*16;

    float q[16];
    const float* qrow = QP + ((size_t)b*LL + l)*CC + cbase;
    #pragma unroll
    for (int i = 0; i < 16; i++) q[i] = qrow[i];

    float acc[16];
    #pragma unroll
    for (int i = 0; i < 16; i++) acc[i] = 0.f;
    float m = -1e30f, denom = 0.f;

    for (int kc0 = 0; kc0 < TK; kc0 += 64) {
        for (int i = tid; i < 64*64; i += 256) {
            int rowk = i >> 6, cc = i & 63;
            size_t src = ((size_t)b*TK + kc0 + rowk)*CC + h*CHD + cc;
            Ks[rowk][cc] = KP[src];
            Vs[rowk][cc] = VP[src];
        }
        __syncthreads();
        for (int j = 0; j < 64; j++) {
            float part = 0.f;
            #pragma unroll
            for (int i = 0; i < 16; i++) part += q[i]*Ks[j][r*16 + i];
            part += __shfl_xor_sync(0xffffffffu, part, 1);
            part += __shfl_xor_sync(0xffffffffu, part, 2);
            float sc = part * 0.125f;
            if (sc > m) {
                float corr = __expf(m - sc);
                denom *= corr;
                #pragma unroll
                for (int i = 0; i < 16; i++) acc[i] *= corr;
                m = sc;
            }
            float p = __expf(sc - m);
            denom += p;
            #pragma unroll
            for (int i = 0; i < 16; i++) acc[i] += p*Vs[j][r*16 + i];
        }
        __syncthreads();
    }
    {
        float part = 0.f;
        #pragma unroll
        for (int i = 0; i < 16; i++) part += q[i]*bk[cbase + i];
        part += __shfl_xor_sync(0xffffffffu, part, 1);
        part += __shfl_xor_sync(0xffffffffu, part, 2);
        float sc = part * 0.125f;
        if (sc > m) {
            float corr = __expf(m - sc);
            denom *= corr;
            #pragma unroll
            for (int i = 0; i < 16; i++) acc[i] *= corr;
            m = sc;
        }
        float p = __expf(sc - m);
        denom += p;
        #pragma unroll
        for (int i = 0; i < 16; i++) acc[i] += p*bv[cbase + i];
    }
    float inv = 1.f / denom;
    size_t obase = ((size_t)b*LL + l)*CC + cbase;
    #pragma unroll
    for (int i = 0; i < 16; i++) {
        __nv_bfloat16 hh, ll; split_bf16(acc[i]*inv, hh, ll);
        AOH[obase + i] = hh; AOL[obase + i] = ll;
    }
}

// ---------------------------- launcher ---------------------------------------
extern "C" void kernel_launch(void* const* d_in, const int* in_sizes, int n_in,
                              void* d_out, int out_size) {
    const float* x         = (const float*)d_in[0];
    const float* q_conv_w  = (const float*)d_in[1];
    const float* q_conv_b  = (const float*)d_in[2];
    const float* q_ln_g    = (const float*)d_in[3];
    const float* q_ln_b    = (const float*)d_in[4];
    const float* kv_conv_w = (const float*)d_in[5];
    const float* kv_conv_b = (const float*)d_in[6];
    const float* k_ln_g    = (const float*)d_in[7];
    const float* k_ln_b    = (const float*)d_in[8];
    const float* v_ln_g    = (const float*)d_in[9];
    const float* v_ln_b    = (const float*)d_in[10];
    const float* in_proj_w = (const float*)d_in[11];
    const float* in_proj_b = (const float*)d_in[12];
    const float* bias_k    = (const float*)d_in[13];
    const float* bias_v    = (const float*)d_in[14];
    const float* out_proj_w= (const float*)d_in[15];
    const float* out_proj_b= (const float*)d_in[16];
    const float* attn_ln_g = (const float*)d_in[17];
    const float* attn_ln_b = (const float*)d_in[18];
    const float* gamma     = (const float*)d_in[19];
    const float* w1        = (const float*)d_in[20];
    const float* b1        = (const float*)d_in[21];
    const float* n1_g      = (const float*)d_in[22];
    const float* n1_b      = (const float*)d_in[23];
    const float* w2        = (const float*)d_in[24];
    const float* b2        = (const float*)d_in[25];
    const float* n2_g      = (const float*)d_in[26];
    const float* n2_b      = (const float*)d_in[27];
    float* out = (float*)d_out;

    float *xt, *q, *kv, *kn, *vt, *pp, *probe, *score, *kp, *vp, *qp, *a, *h1, *h2;
    int* idx;
    __nv_bfloat16 *xth,*xtl,*qh,*ql,*kch,*kcl,*vch,*vcl,*aoh,*aol,*ah,*al,*h1h,*h1l;
    __nv_bfloat16 *wqh,*wql,*wkvh,*wkvl,*winh,*winl,*woh,*wol,*w1h,*w1l,*w2h,*w2l;

    cudaGetSymbolAddress((void**)&xt,   g_xt);
    cudaGetSymbolAddress((void**)&q,    g_q);
    cudaGetSymbolAddress((void**)&kv,   g_kv);
    cudaGetSymbolAddress((void**)&kn,   g_kn);
    cudaGetSymbolAddress((void**)&vt,   g_vt);
    cudaGetSymbolAddress((void**)&pp,   g_pp);
    cudaGetSymbolAddress((void**)&probe,g_probe);
    cudaGetSymbolAddress((void**)&score,g_score);
    cudaGetSymbolAddress((void**)&idx,  g_idx);
    cudaGetSymbolAddress((void**)&kp,   g_kp);
    cudaGetSymbolAddress((void**)&vp,   g_vp);
    cudaGetSymbolAddress((void**)&qp,   g_qp);
    cudaGetSymbolAddress((void**)&a,    g_a);
    cudaGetSymbolAddress((void**)&h1,   g_h1);
    cudaGetSymbolAddress((void**)&h2,   g_h2);
    cudaGetSymbolAddress((void**)&xth,  g_xt_h); cudaGetSymbolAddress((void**)&xtl, g_xt_l);
    cudaGetSymbolAddress((void**)&qh,   g_q_h);  cudaGetSymbolAddress((void**)&ql,  g_q_l);
    cudaGetSymbolAddress((void**)&kch,  g_kc_h); cudaGetSymbolAddress((void**)&kcl, g_kc_l);
    cudaGetSymbolAddress((void**)&vch,  g_vc_h); cudaGetSymbolAddress((void**)&vcl, g_vc_l);
    cudaGetSymbolAddress((void**)&aoh,  g_ao_h); cudaGetSymbolAddress((void**)&aol, g_ao_l);
    cudaGetSymbolAddress((void**)&ah,   g_a_h);  cudaGetSymbolAddress((void**)&al,  g_a_l);
    cudaGetSymbolAddress((void**)&h1h,  g_h1_h); cudaGetSymbolAddress((void**)&h1l, g_h1_l);
    cudaGetSymbolAddress((void**)&wqh,  g_wq_h); cudaGetSymbolAddress((void**)&wql, g_wq_l);
    cudaGetSymbolAddress((void**)&wkvh, g_wkv_h);cudaGetSymbolAddress((void**)&wkvl,g_wkv_l);
    cudaGetSymbolAddress((void**)&winh, g_win_h);cudaGetSymbolAddress((void**)&winl,g_win_l);
    cudaGetSymbolAddress((void**)&woh,  g_wo_h); cudaGetSymbolAddress((void**)&wol, g_wo_l);
    cudaGetSymbolAddress((void**)&w1h,  g_w1_h); cudaGetSymbolAddress((void**)&w1l, g_w1_l);
    cudaGetSymbolAddress((void**)&w2h,  g_w2_h); cudaGetSymbolAddress((void**)&w2l, g_w2_l);

    cudaFuncSetAttribute(k_gemm_mma, cudaFuncAttributeMaxDynamicSharedMemorySize, 3*STG);
    const int GS = 3*STG;   // 184320

    // weight conversions
    k_cvt<<<(CC*CC)/1024,   256>>>(q_conv_w,  wqh,  wql,  CC*CC);
    k_cvt<<<(2*CC*CC)/1024, 256>>>(kv_conv_w, wkvh, wkvl, 2*CC*CC);
    k_cvt<<<(3*CC*CC)/1024, 256>>>(in_proj_w, winh, winl, 3*CC*CC);
    k_cvt<<<(CC*CC)/1024,   256>>>(out_proj_w,woh,  wol,  CC*CC);
    k_cvt<<<(MM*CC)/1024,   256>>>(w1,        w1h,  w1l,  MM*CC);
    k_cvt<<<(CC*MM)/1024,   256>>>(w2,        w2h,  w2l,  CC*MM);

    dim3 tgrid(LL/32, CC/32, BB), tblk(32, 8);
    k_transpose_in<<<tgrid, tblk>>>(x, xt, xth, xtl);

    // Q / KV projections
    k_gemm_mma<<<dim3(CC/256,   BLROWS/128), 512, GS>>>(xth, xtl, wqh,  wql,  q_conv_b,  q,  CC,   CC);
    k_gemm_mma<<<dim3(2*CC/256, BLROWS/128), 512, GS>>>(xth, xtl, wkvh, wkvl, kv_conv_b, kv, 2*CC, CC);

    // LayerNorms (+l2n for Q,K)
    k_ln512<<<BLROWS/8, 256>>>(q,       CC,   q,  q_ln_g, q_ln_b, 1, nullptr, nullptr, qh, ql);
    k_ln512<<<BLROWS/8, 256>>>(kv,      2*CC, kn, k_ln_g, k_ln_b, 1, nullptr, nullptr, nullptr, nullptr);
    k_ln512<<<BLROWS/8, 256>>>(kv + CC, 2*CC, vt, v_ln_g, v_ln_b, 0, nullptr, nullptr, nullptr, nullptr);

    // probe, score, top-k, gather
    k_probe_partial<<<dim3(BB, 32), CC>>>(q, pp);
    k_probe_reduce<<<BB, CC>>>(pp, probe);
    k_score<<<(BB*LL*32)/256, 256>>>(kn, probe, score);
    k_topk<<<BB*HH, 512>>>(score, idx);
    k_gather<<<BB*TK, CC>>>(kn, vt, idx, kch, kcl, vch, vcl);

    // in_proj
    k_gemm_mma<<<dim3(CC/256, BLROWS/128),  512, GS>>>(qh,  ql,  winh,           winl,           in_proj_b,        qp, CC, CC);
    k_gemm_mma<<<dim3(CC/256, (BB*TK)/128), 512, GS>>>(kch, kcl, winh + CC*CC,   winl + CC*CC,   in_proj_b + CC,   kp, CC, CC);
    k_gemm_mma<<<dim3(CC/256, (BB*TK)/128), 512, GS>>>(vch, vcl, winh + 2*CC*CC, winl + 2*CC*CC, in_proj_b + 2*CC, vp, CC, CC);

    // attention (257 keys: 256 selected + bias key) -> bf16 hi/lo
    k_attn<<<dim3(LL/64, BB*HH), 256>>>(qp, kp, vp, bias_k, bias_v, aoh, aol);

    // out_proj -> h2(temp), attn LN * gamma + x residual -> a (+ hi/lo)
    k_gemm_mma<<<dim3(CC/256, BLROWS/128), 512, GS>>>(aoh, aol, woh, wol, out_proj_b, h2, CC, CC);
    k_ln512<<<BLROWS/8, 256>>>(h2, CC, a, attn_ln_g, attn_ln_b, 2, gamma, xt, ah, al);

    // FFN
    k_gemm_mma<<<dim3(MM/256, BLROWS/128), 512, GS>>>(ah, al, w1h, w1l, b1, h1, MM, CC);
    k_ln2048<<<BLROWS/8, 256>>>(h1, n1_g, n1_b, h1h, h1l);
    k_gemm_mma<<<dim3(CC/256, BLROWS/128), 512, GS>>>(h1h, h1l, w2h, w2l, b2, h2, CC, MM);
    k_ln512<<<BLROWS/8, 256>>>(h2, CC, h2, n2_g, n2_b, 3, nullptr, nullptr, nullptr, nullptr);

    // out = transpose(h2 + a)
    k_add_transpose_out<<<tgrid, tblk>>>(h2, a, out);
}

// round 7
// speedup vs baseline: 1.2075x; 1.2075x over previous
#include <cuda_runtime.h>
#include <cuda_fp16.h>
#include <math.h>
#include <stdint.h>

// Problem constants
#define BB   8
#define CC   512
#define LL   4096
#define HH   8
#define TK   256
#define MM   2048
#define CHD  64
#define BLROWS (BB*LL)   // 32768

// ---------------- scratch (device globals; no allocation allowed) ----------
__device__ __align__(16) float g_xt  [(size_t)BB*LL*CC];
__device__ __align__(16) float g_q   [(size_t)BB*LL*CC];
__device__ __align__(16) float g_kv  [(size_t)BB*LL*2*CC];
__device__ __align__(16) float g_kn  [(size_t)BB*LL*CC];
__device__ __align__(16) float g_vt  [(size_t)BB*LL*CC];
__device__ __align__(16) float g_pp  [(size_t)BB*32*CC];
__device__ __align__(16) float g_probe[BB*CC];
__device__ __align__(16) float g_score[BB*HH*LL];
__device__ __align__(16) int   g_idx [BB*HH*TK];
__device__ __align__(16) float g_kp  [(size_t)BB*TK*CC];
__device__ __align__(16) float g_vp  [(size_t)BB*TK*CC];
__device__ __align__(16) float g_qp  [(size_t)BB*LL*CC];
__device__ __align__(16) float g_a   [(size_t)BB*LL*CC];
__device__ __align__(16) float g_h2  [(size_t)BB*LL*CC];
__device__ __align__(16) float g_h1  [(size_t)BB*LL*MM];

// fp16 hi/lo split activations
__device__ __align__(16) __half g_xt_h[(size_t)BB*LL*CC];
__device__ __align__(16) __half g_xt_l[(size_t)BB*LL*CC];
__device__ __align__(16) __half g_q_h [(size_t)BB*LL*CC];
__device__ __align__(16) __half g_q_l [(size_t)BB*LL*CC];
__device__ __align__(16) __half g_kc_h[(size_t)BB*TK*CC];
__device__ __align__(16) __half g_kc_l[(size_t)BB*TK*CC];
__device__ __align__(16) __half g_vc_h[(size_t)BB*TK*CC];
__device__ __align__(16) __half g_vc_l[(size_t)BB*TK*CC];
__device__ __align__(16) __half g_ao_h[(size_t)BB*LL*CC];
__device__ __align__(16) __half g_ao_l[(size_t)BB*LL*CC];
__device__ __align__(16) __half g_a_h [(size_t)BB*LL*CC];
__device__ __align__(16) __half g_h1_h[(size_t)BB*LL*MM];

// fp16 hi/lo weights
__device__ __align__(16) __half g_wq_h [CC*CC],    g_wq_l [CC*CC];
__device__ __align__(16) __half g_wkv_h[2*CC*CC],  g_wkv_l[2*CC*CC];
__device__ __align__(16) __half g_win_h[3*CC*CC],  g_win_l[3*CC*CC];
__device__ __align__(16) __half g_wo_h [CC*CC],    g_wo_l [CC*CC];
__device__ __align__(16) __half g_w1_h [MM*CC];
__device__ __align__(16) __half g_w2_h [CC*MM];

// ================= helpers ===================================================
static __device__ __forceinline__ uint32_t smem_u32(const void* p) {
    uint32_t a;
    asm("{ .reg .u64 t; cvta.to.shared.u64 t, %1; cvt.u32.u64 %0, t; }"
        : "=r"(a) : "l"(p));
    return a;
}
static __device__ __forceinline__ void split_f16(float v, __half& h, __half& l) {
    h = __float2half(v);
    l = __float2half(v - __half2float(h));
}
static __device__ __forceinline__ void ldmA(uint32_t* r, uint32_t addr) {
    asm volatile("ldmatrix.sync.aligned.m8n8.x4.shared.b16 {%0,%1,%2,%3}, [%4];"
                 : "=r"(r[0]), "=r"(r[1]), "=r"(r[2]), "=r"(r[3]) : "r"(addr));
}
static __device__ __forceinline__ void ldmB4(uint32_t* r, uint32_t addr) {
    asm volatile("ldmatrix.sync.aligned.m8n8.x4.shared.b16 {%0,%1,%2,%3}, [%4];"
                 : "=r"(r[0]), "=r"(r[1]), "=r"(r[2]), "=r"(r[3]) : "r"(addr));
}
static __device__ __forceinline__ void mma16816(float* d, const uint32_t* a, const uint32_t* b) {
    asm volatile(
        "mma.sync.aligned.m16n8k16.row.col.f32.f16.f16.f32 "
        "{%0,%1,%2,%3}, {%4,%5,%6,%7}, {%8,%9}, {%0,%1,%2,%3};"
        : "+f"(d[0]), "+f"(d[1]), "+f"(d[2]), "+f"(d[3])
        : "r"(a[0]), "r"(a[1]), "r"(a[2]), "r"(a[3]), "r"(b[0]), "r"(b[1]));
}
static __device__ __forceinline__ void cpasync16(uint32_t saddr, const void* gaddr) {
    asm volatile("cp.async.cg.shared.global [%0], [%1], 16;"
                 :: "r"(saddr), "l"(gaddr) : "memory");
}

// ================= tensor-core GEMM via mma.sync ============================
// Y(row,col) = X(row,K) * W(col,K)^T + bias[col]
// CTA tile 128x256, BK=32, 512 threads = 16 warps (4M x 4N), warp tile 32x64.
// NPROD==3: fp16 hi/lo split, D += Ah*Bh + Ah*Bl + Al*Bh (near-fp32 exact)
// NPROD==1: plain fp16 single product (D += Ah*Bh)
#define AH_OFF 0
#define AL_OFF 10240
#define BH_OFF 20480
#define BL_OFF 40960
#define STG    61440
template<int NPROD>
__global__ void __launch_bounds__(512, 1) k_gemm_mma(
    const __half* __restrict__ Ah, const __half* __restrict__ Al,
    const __half* __restrict__ Bh, const __half* __restrict__ Bl,
    const float* __restrict__ bias, float* __restrict__ Y, int N, int K)
{
    extern __shared__ __align__(128) char smem[];
    const uint32_t sb = smem_u32(smem);
    const int tid  = threadIdx.x;
    const int wid  = tid >> 5, lane = tid & 31;
    const int wm   = wid & 3;              // warp M 0..3 (32 rows)
    const int wn   = wid >> 2;             // warp N 0..3 (64 cols)
    const int bm = blockIdx.y << 7, bn = blockIdx.x << 8;

    const int nch = K >> 5;                // chunks of BK=32

    float acc[2][8][4];
    #pragma unroll
    for (int m = 0; m < 2; m++)
        #pragma unroll
        for (int n = 0; n < 8; n++)
            #pragma unroll
            for (int v = 0; v < 4; v++) acc[m][n][v] = 0.f;

    // ---- async load of one chunk into stage s ----
    auto load_chunk = [&](int ck, int s) {
        const int k0 = ck << 5;
        const uint32_t so = sb + s * STG;
        if (NPROD == 3) {
            #pragma unroll
            for (int i = 0; i < 6; i++) {
                const int idx = tid + (i << 9);   // 0..3071 16B units
                const __half* src;
                int local; uint32_t dst; int rb;
                if (i < 1)      { src = Ah; local = idx;        dst = AH_OFF; rb = bm; }
                else if (i < 2) { src = Al; local = idx - 512;  dst = AL_OFF; rb = bm; }
                else if (i < 4) { src = Bh; local = idx - 1024; dst = BH_OFF; rb = bn; }
                else            { src = Bl; local = idx - 2048; dst = BL_OFF; rb = bn; }
                const int row = local >> 2, seg = local & 3;
                cpasync16(so + dst + row * 80 + (seg << 4),
                          src + (size_t)(rb + row) * K + k0 + (seg << 3));
            }
        } else {
            #pragma unroll
            for (int i = 0; i < 3; i++) {
                const int idx = tid + (i << 9);   // 0..1535 16B units
                const __half* src;
                int local; uint32_t dst; int rb;
                if (i < 1) { src = Ah; local = idx;       dst = AH_OFF; rb = bm; }
                else       { src = Bh; local = idx - 512; dst = BH_OFF; rb = bn; }
                const int row = local >> 2, seg = local & 3;
                cpasync16(so + dst + row * 80 + (seg << 4),
                          src + (size_t)(rb + row) * K + k0 + (seg << 3));
            }
        }
        asm volatile("cp.async.commit_group;" ::: "memory");
    };

    load_chunk(0, 0);
    load_chunk(1, 1);

    // ldmatrix lane offsets
    const uint32_t aRow = (lane & 7) + ((lane >> 3) & 1) * 8;
    const uint32_t aKof = (lane >> 4) * 8;
    // B x4: lanes 0-7 -> rows+0 k0, 8-15 -> rows+0 k8, 16-23 -> rows+8 k0, 24-31 -> rows+8 k8
    const uint32_t bRow = (lane & 7) + ((lane >> 4) & 1) * 8;
    const uint32_t bKof = ((lane >> 3) & 1) * 8;

    for (int ck = 0; ck < nch; ck++) {
        if (ck + 2 < nch) {
            load_chunk(ck + 2, (ck + 2) % 3);
            asm volatile("cp.async.wait_group 2;" ::: "memory");
        } else if (ck + 1 < nch) {
            asm volatile("cp.async.wait_group 1;" ::: "memory");
        } else {
            asm volatile("cp.async.wait_group 0;" ::: "memory");
        }
        __syncthreads();

        const uint32_t so = sb + (ck % 3) * STG;
        #pragma unroll
        for (int ks = 0; ks < 2; ks++) {
            uint32_t ah[2][4], al[2][4];
            #pragma unroll
            for (int mf = 0; mf < 2; mf++) {
                uint32_t row = wm * 32 + mf * 16 + aRow;
                uint32_t off = row * 80 + (aKof + ks * 16) * 2;
                ldmA(ah[mf], so + AH_OFF + off);
                if (NPROD == 3) ldmA(al[mf], so + AL_OFF + off);
            }
            #pragma unroll
            for (int ntp = 0; ntp < 4; ntp++) {        // pairs of n-tiles
                uint32_t row = wn * 64 + ntp * 16 + bRow;
                uint32_t off = row * 80 + (bKof + ks * 16) * 2;
                uint32_t bh[4], bl[4];
                ldmB4(bh, so + BH_OFF + off);
                if (NPROD == 3) ldmB4(bl, so + BL_OFF + off);
                #pragma unroll
                for (int sub = 0; sub < 2; sub++) {
                    const int nt = ntp * 2 + sub;
                    #pragma unroll
                    for (int mf = 0; mf < 2; mf++) {
                        mma16816(acc[mf][nt], ah[mf], bh + 2*sub);
                        if (NPROD == 3) {
                            mma16816(acc[mf][nt], ah[mf], bl + 2*sub);
                            mma16816(acc[mf][nt], al[mf], bh + 2*sub);
                        }
                    }
                }
            }
        }
        __syncthreads();
    }

    // ---- epilogue: bias add, direct fp32 stores ----
    const int r  = lane >> 2;
    const int c2 = (lane & 3) << 1;
    #pragma unroll
    for (int mf = 0; mf < 2; mf++) {
        const int gm = bm + wm * 32 + mf * 16;
        #pragma unroll
        for (int nt = 0; nt < 8; nt++) {
            const int gn = bn + wn * 64 + nt * 8 + c2;
            float bx = bias[gn], by = bias[gn + 1];
            float2 v0 = make_float2(acc[mf][nt][0] + bx, acc[mf][nt][1] + by);
            float2 v1 = make_float2(acc[mf][nt][2] + bx, acc[mf][nt][3] + by);
            *(float2*)(Y + (size_t)(gm + r) * N + gn)     = v0;
            *(float2*)(Y + (size_t)(gm + r + 8) * N + gn) = v1;
        }
    }
}

// ---------------- weight fp32 -> fp16 hi/lo ---------------------------------
__global__ void k_cvt(const float* __restrict__ x, __half* __restrict__ h,
                      __half* __restrict__ l, int n) {
    int i = (blockIdx.x * 256 + threadIdx.x) * 4;
    if (i >= n) return;
    float4 v = *(const float4*)(x + i);
    __half hh, ll;
    split_f16(v.x, hh, ll); h[i+0] = hh; if (l) l[i+0] = ll;
    split_f16(v.y, hh, ll); h[i+1] = hh; if (l) l[i+1] = ll;
    split_f16(v.z, hh, ll); h[i+2] = hh; if (l) l[i+2] = ll;
    split_f16(v.w, hh, ll); h[i+3] = hh; if (l) l[i+3] = ll;
}

// ---------------- transpose (B,C,L) -> (B,L,C), fp32 + fp16 hi/lo ----------
__global__ void k_transpose_in(const float* __restrict__ X, float* __restrict__ Y,
                               __half* __restrict__ YH, __half* __restrict__ YL) {
    __shared__ float tile[32][33];
    int b  = blockIdx.z;
    int l0 = blockIdx.x << 5, c0 = blockIdx.y << 5;
    int tx = threadIdx.x, ty = threadIdx.y;
    const float* Xb = X + (size_t)b*CC*LL;
    #pragma unroll
    for (int i = ty; i < 32; i += 8)
        tile[i][tx] = Xb[(size_t)(c0+i)*LL + l0 + tx];
    __syncthreads();
    size_t base = (size_t)b*LL*CC;
    #pragma unroll
    for (int i = ty; i < 32; i += 8) {
        float v = tile[tx][i];
        size_t o = base + (size_t)(l0+i)*CC + c0 + tx;
        Y[o] = v;
        __half hh, ll; split_f16(v, hh, ll);
        YH[o] = hh; YL[o] = ll;
    }
}

// ---------------- out = transpose(H + A), (B,L,C) -> (B,C,L) ---------------
__global__ void k_add_transpose_out(const float* __restrict__ Hh, const float* __restrict__ A,
                                    float* __restrict__ OUT) {
    __shared__ float tile[32][33];
    int b  = blockIdx.z;
    int l0 = blockIdx.x << 5, c0 = blockIdx.y << 5;
    int tx = threadIdx.x, ty = threadIdx.y;
    const float* Hb = Hh + (size_t)b*LL*CC;
    const float* Ab = A  + (size_t)b*LL*CC;
    #pragma unroll
    for (int i = ty; i < 32; i += 8) {
        size_t o = (size_t)(l0+i)*CC + c0 + tx;
        tile[i][tx] = Hb[o] + Ab[o];
    }
    __syncthreads();
    float* Ob = OUT + (size_t)b*CC*LL;
    #pragma unroll
    for (int i = ty; i < 32; i += 8)
        Ob[(size_t)(c0+i)*LL + l0 + tx] = tile[tx][i];
}

// ---------------- warp-per-row LayerNorm, Wd=512, fused epilogues -----------
// mode 0: plain LN ; 1: LN + per-64-chunk l2n ; 2: LN*gamma + resid ; 3: relu
__global__ void k_ln512(const float* __restrict__ in, int ld_in,
                        float* __restrict__ out,
                        const float* __restrict__ gam, const float* __restrict__ bet,
                        int mode, const float* __restrict__ gamma_p,
                        const float* __restrict__ resid,
                        __half* __restrict__ oh, __half* __restrict__ ol) {
    const int lane = threadIdx.x & 31;
    const int row  = blockIdx.x * 8 + (threadIdx.x >> 5);
    const float* xr = in + (size_t)row * ld_in + lane * 16;

    float v[16];
    float s = 0.f, s2 = 0.f;
    #pragma unroll
    for (int j = 0; j < 16; j += 4) {
        float4 t = *(const float4*)(xr + j);
        v[j]=t.x; v[j+1]=t.y; v[j+2]=t.z; v[j+3]=t.w;
        s += t.x+t.y+t.z+t.w;
        s2 += t.x*t.x+t.y*t.y+t.z*t.z+t.w*t.w;
    }
    #pragma unroll
    for (int o = 16; o > 0; o >>= 1) {
        s  += __shfl_xor_sync(0xffffffffu, s,  o);
        s2 += __shfl_xor_sync(0xffffffffu, s2, o);
    }
    const float mu = s * (1.f/512.f);
    const float rstd = rsqrtf(s2 * (1.f/512.f) - mu*mu + 1e-5f);

    float y[16];
    const int cb = lane * 16;
    #pragma unroll
    for (int i = 0; i < 16; i++)
        y[i] = (v[i] - mu) * rstd * gam[cb + i] + bet[cb + i];

    if (mode == 1) {           // l2n over 64-ch chunk = 4 adjacent lanes
        float qq = 0.f;
        #pragma unroll
        for (int i = 0; i < 16; i++) qq += y[i]*y[i];
        qq += __shfl_xor_sync(0xffffffffu, qq, 1);
        qq += __shfl_xor_sync(0xffffffffu, qq, 2);
        float sc = 1.f / fmaxf(sqrtf(qq), 1e-12f);
        #pragma unroll
        for (int i = 0; i < 16; i++) y[i] *= sc;
    } else if (mode == 2) {
        float gsc = gamma_p[0];
        const float* rr = resid + (size_t)row * 512 + cb;
        #pragma unroll
        for (int i = 0; i < 16; i++) y[i] = y[i]*gsc + rr[i];
    } else if (mode == 3) {
        #pragma unroll
        for (int i = 0; i < 16; i++) y[i] = fmaxf(y[i], 0.f);
    }
    size_t ob = (size_t)row * 512 + cb;
    if (out) {
        #pragma unroll
        for (int j = 0; j < 16; j += 4)
            *(float4*)(out + ob + j) = make_float4(y[j], y[j+1], y[j+2], y[j+3]);
    }
    if (oh) {
        #pragma unroll
        for (int i = 0; i < 16; i++) {
            __half hh, ll; split_f16(y[i], hh, ll);
            oh[ob + i] = hh;
            if (ol) ol[ob + i] = ll;
        }
    }
}

// ---------------- warp-per-row LN+relu, Wd=2048, fp16 hi out only -----------
__global__ void k_ln2048(const float* __restrict__ in,
                         const float* __restrict__ gam, const float* __restrict__ bet,
                         __half* __restrict__ oh) {
    const int lane = threadIdx.x & 31;
    const int row  = blockIdx.x * 8 + (threadIdx.x >> 5);
    const float* xr = in + (size_t)row * 2048;

    float s = 0.f, s2 = 0.f;
    #pragma unroll
    for (int w = 0; w < 16; w++) {
        float4 t = *(const float4*)(xr + ((w*32 + lane) << 2));
        s  += t.x+t.y+t.z+t.w;
        s2 += t.x*t.x+t.y*t.y+t.z*t.z+t.w*t.w;
    }
    #pragma unroll
    for (int o = 16; o > 0; o >>= 1) {
        s  += __shfl_xor_sync(0xffffffffu, s,  o);
        s2 += __shfl_xor_sync(0xffffffffu, s2, o);
    }
    const float mu = s * (1.f/2048.f);
    const float rstd = rsqrtf(s2 * (1.f/2048.f) - mu*mu + 1e-5f);

    #pragma unroll
    for (int w = 0; w < 16; w++) {
        const int e = (w*32 + lane) << 2;
        float4 t = *(const float4*)(xr + e);
        float4 g = *(const float4*)(gam + e);
        float4 bb = *(const float4*)(bet + e);
        float y0 = fmaxf((t.x-mu)*rstd*g.x + bb.x, 0.f);
        float y1 = fmaxf((t.y-mu)*rstd*g.y + bb.y, 0.f);
        float y2 = fmaxf((t.z-mu)*rstd*g.z + bb.z, 0.f);
        float y3 = fmaxf((t.w-mu)*rstd*g.w + bb.w, 0.f);
        size_t ob = (size_t)row * 2048 + e;
        __half2* dst = (__half2*)(oh + ob);
        dst[0] = __floats2half2_rn(y0, y1);
        dst[1] = __floats2half2_rn(y2, y3);
    }
}

// ---------------- q_probe = sum over L of QN --------------------------------
__global__ void k_probe_partial(const float* __restrict__ QN, float* __restrict__ part) {
    int b = blockIdx.x, ch = blockIdx.y;
    int c = threadIdx.x;
    const int CHUNK = LL / 32;
    const float* p = QN + ((size_t)b*LL + (size_t)ch*CHUNK)*CC + c;
    float s = 0.f;
    for (int i = 0; i < CHUNK; i++) s += p[(size_t)i*CC];
    part[((size_t)b*32 + ch)*CC + c] = s;
}
__global__ void k_probe_reduce(const float* __restrict__ part, float* __restrict__ probe) {
    int b = blockIdx.x; int c = threadIdx.x;
    float s = 0.f;
    for (int ch = 0; ch < 32; ch++) s += part[((size_t)b*32 + ch)*CC + c];
    probe[b*CC + c] = s;
}

// ---------------- score[b,h,l] = probe . (|k|+k) -----------------------------
__global__ void k_score(const float* __restrict__ KN, const float* __restrict__ probe,
                        float* __restrict__ score) {
    int gw   = (blockIdx.x * blockDim.x + threadIdx.x) >> 5;
    int lane = threadIdx.x & 31;
    if (gw >= BB*LL) return;
    int b = gw >> 12;
    int l = gw & (LL-1);
    const float* krow = KN + (size_t)gw*CC;
    const float* pr   = probe + b*CC;
    int c0 = lane << 4;
    float s = 0.f;
    #pragma unroll
    for (int j = 0; j < 16; j += 4) {
        float4 k4 = *(const float4*)(krow + c0 + j);
        float4 p4 = *(const float4*)(pr   + c0 + j);
        s += p4.x*(fabsf(k4.x)+k4.x) + p4.y*(fabsf(k4.y)+k4.y)
           + p4.z*(fabsf(k4.z)+k4.z) + p4.w*(fabsf(k4.w)+k4.w);
    }
    s += __shfl_xor_sync(0xffffffffu, s, 1);
    s += __shfl_xor_sync(0xffffffffu, s, 2);
    if ((lane & 3) == 0) {
        int h = lane >> 2;
        score[((size_t)(b*HH + h))*LL + l] = s;
    }
}

// ---------------- exact top-k via in-smem bitonic sort -----------------------
__global__ void k_topk(const float* __restrict__ score, int* __restrict__ idx) {
    __shared__ unsigned long long keys[LL];
    int bh = blockIdx.x;
    const float* s = score + (size_t)bh*LL;
    for (int i = threadIdx.x; i < LL; i += blockDim.x) {
        unsigned u = __float_as_uint(s[i]);
        u = (u & 0x80000000u) ? ~u : (u | 0x80000000u);
        keys[i] = ((unsigned long long)u << 32) | (unsigned)(LL-1-i);
    }
    __syncthreads();
    for (int k = 2; k <= LL; k <<= 1) {
        for (int j = k >> 1; j > 0; j >>= 1) {
            for (int i = threadIdx.x; i < LL; i += blockDim.x) {
                int ixj = i ^ j;
                if (ixj > i) {
                    unsigned long long a = keys[i], c = keys[ixj];
                    bool desc = (i & k) == 0;
                    if (desc ? (a < c) : (a > c)) { keys[i] = c; keys[ixj] = a; }
                }
            }
            __syncthreads();
        }
    }
    for (int t = threadIdx.x; t < TK; t += blockDim.x)
        idx[bh*TK + t] = (LL-1) - (int)(unsigned)(keys[t] & 0xffffffffu);
}

// ---------------- gather selected K/V rows per head -> fp16 hi/lo ------------
__global__ void k_gather(const float* __restrict__ KN, const float* __restrict__ VT,
                         const int* __restrict__ idx,
                         __half* __restrict__ KCH, __half* __restrict__ KCL,
                         __half* __restrict__ VCH, __half* __restrict__ VCL) {
    int bt = blockIdx.x;
    int b = bt / TK, t = bt % TK;
    int c = threadIdx.x;
    int h = c >> 6;
    int l = idx[(b*HH + h)*TK + t];
    size_t src = ((size_t)b*LL + l)*CC + c;
    size_t dst = (size_t)bt*CC + c;
    __half hh, ll;
    split_f16(KN[src], hh, ll); KCH[dst] = hh; KCL[dst] = ll;
    split_f16(VT[src], hh, ll); VCH[dst] = hh; VCL[dst] = ll;
}

// ---------------- attention: per (b,h,64-query tile), online softmax ---------
__global__ void k_attn(const float* __restrict__ QP, const float* __restrict__ KP,
                       const float* __restrict__ VP, const float* __restrict__ bk,
                       const float* __restrict__ bv,
                       __half* __restrict__ AOH, __half* __restrict__ AOL) {
    __shared__ float Ks[64][64];
    __shared__ float Vs[64][64];
    int bh = blockIdx.y;
    int b = bh >> 3, h = bh & 7;
    int l0 = blockIdx.x << 6;
    int tid = threadIdx.x;
    int g = tid >> 2;
    int r = tid & 3;
    int l = l0 + g;
    const int cbase = h*CHD + r*16;

    float q[16];
    const float* qrow = QP + ((size_t)b*LL + l)*CC + cbase;
    #pragma unroll
    for (int i = 0; i < 16; i++) q[i] = qrow[i];

    float acc[16];
    #pragma unroll
    for (int i = 0; i < 16; i++) acc[i] = 0.f;
    float m = -1e30f, denom = 0.f;

    for (int kc0 = 0; kc0 < TK; kc0 += 64) {
        for (int i = tid; i < 64*64; i += 256) {
            int rowk = i >> 6, cc = i & 63;
            size_t src = ((size_t)b*TK + kc0 + rowk)*CC + h*CHD + cc;
            Ks[rowk][cc] = KP[src];
            Vs[rowk][cc] = VP[src];
        }
        __syncthreads();
        for (int j = 0; j < 64; j++) {
            float part = 0.f;
            #pragma unroll
            for (int i = 0; i < 16; i++) part += q[i]*Ks[j][r*16 + i];
            part += __shfl_xor_sync(0xffffffffu, part, 1);
            part += __shfl_xor_sync(0xffffffffu, part, 2);
            float sc = part * 0.125f;
            if (sc > m) {
                float corr = __expf(m - sc);
                denom *= corr;
                #pragma unroll
                for (int i = 0; i < 16; i++) acc[i] *= corr;
                m = sc;
            }
            float p = __expf(sc - m);
            denom += p;
            #pragma unroll
            for (int i = 0; i < 16; i++) acc[i] += p*Vs[j][r*16 + i];
        }
        __syncthreads();
    }
    {
        float part = 0.f;
        #pragma unroll
        for (int i = 0; i < 16; i++) part += q[i]*bk[cbase + i];
        part += __shfl_xor_sync(0xffffffffu, part, 1);
        part += __shfl_xor_sync(0xffffffffu, part, 2);
        float sc = part * 0.125f;
        if (sc > m) {
            float corr = __expf(m - sc);
            denom *= corr;
            #pragma unroll
            for (int i = 0; i < 16; i++) acc[i] *= corr;
            m = sc;
        }
        float p = __expf(sc - m);
        denom += p;
        #pragma unroll
        for (int i = 0; i < 16; i++) acc[i] += p*bv[cbase + i];
    }
    float inv = 1.f / denom;
    size_t obase = ((size_t)b*LL + l)*CC + cbase;
    #pragma unroll
    for (int i = 0; i < 16; i++) {
        __half hh, ll; split_f16(acc[i]*inv, hh, ll);
        AOH[obase + i] = hh; AOL[obase + i] = ll;
    }
}

// ---------------------------- launcher ---------------------------------------
extern "C" void kernel_launch(void* const* d_in, const int* in_sizes, int n_in,
                              void* d_out, int out_size) {
    const float* x         = (const float*)d_in[0];
    const float* q_conv_w  = (const float*)d_in[1];
    const float* q_conv_b  = (const float*)d_in[2];
    const float* q_ln_g    = (const float*)d_in[3];
    const float* q_ln_b    = (const float*)d_in[4];
    const float* kv_conv_w = (const float*)d_in[5];
    const float* kv_conv_b = (const float*)d_in[6];
    const float* k_ln_g    = (const float*)d_in[7];
    const float* k_ln_b    = (const float*)d_in[8];
    const float* v_ln_g    = (const float*)d_in[9];
    const float* v_ln_b    = (const float*)d_in[10];
    const float* in_proj_w = (const float*)d_in[11];
    const float* in_proj_b = (const float*)d_in[12];
    const float* bias_k    = (const float*)d_in[13];
    const float* bias_v    = (const float*)d_in[14];
    const float* out_proj_w= (const float*)d_in[15];
    const float* out_proj_b= (const float*)d_in[16];
    const float* attn_ln_g = (const float*)d_in[17];
    const float* attn_ln_b = (const float*)d_in[18];
    const float* gamma     = (const float*)d_in[19];
    const float* w1        = (const float*)d_in[20];
    const float* b1        = (const float*)d_in[21];
    const float* n1_g      = (const float*)d_in[22];
    const float* n1_b      = (const float*)d_in[23];
    const float* w2        = (const float*)d_in[24];
    const float* b2        = (const float*)d_in[25];
    const float* n2_g      = (const float*)d_in[26];
    const float* n2_b      = (const float*)d_in[27];
    float* out = (float*)d_out;

    float *xt, *q, *kv, *kn, *vt, *pp, *probe, *score, *kp, *vp, *qp, *a, *h1, *h2;
    int* idx;
    __half *xth,*xtl,*qh,*ql,*kch,*kcl,*vch,*vcl,*aoh,*aol,*ah,*h1h;
    __half *wqh,*wql,*wkvh,*wkvl,*winh,*winl,*woh,*wol,*w1h,*w2h;

    cudaGetSymbolAddress((void**)&xt,   g_xt);
    cudaGetSymbolAddress((void**)&q,    g_q);
    cudaGetSymbolAddress((void**)&kv,   g_kv);
    cudaGetSymbolAddress((void**)&kn,   g_kn);
    cudaGetSymbolAddress((void**)&vt,   g_vt);
    cudaGetSymbolAddress((void**)&pp,   g_pp);
    cudaGetSymbolAddress((void**)&probe,g_probe);
    cudaGetSymbolAddress((void**)&score,g_score);
    cudaGetSymbolAddress((void**)&idx,  g_idx);
    cudaGetSymbolAddress((void**)&kp,   g_kp);
    cudaGetSymbolAddress((void**)&vp,   g_vp);
    cudaGetSymbolAddress((void**)&qp,   g_qp);
    cudaGetSymbolAddress((void**)&a,    g_a);
    cudaGetSymbolAddress((void**)&h1,   g_h1);
    cudaGetSymbolAddress((void**)&h2,   g_h2);
    cudaGetSymbolAddress((void**)&xth,  g_xt_h); cudaGetSymbolAddress((void**)&xtl, g_xt_l);
    cudaGetSymbolAddress((void**)&qh,   g_q_h);  cudaGetSymbolAddress((void**)&ql,  g_q_l);
    cudaGetSymbolAddress((void**)&kch,  g_kc_h); cudaGetSymbolAddress((void**)&kcl, g_kc_l);
    cudaGetSymbolAddress((void**)&vch,  g_vc_h); cudaGetSymbolAddress((void**)&vcl, g_vc_l);
    cudaGetSymbolAddress((void**)&aoh,  g_ao_h); cudaGetSymbolAddress((void**)&aol, g_ao_l);
    cudaGetSymbolAddress((void**)&ah,   g_a_h);
    cudaGetSymbolAddress((void**)&h1h,  g_h1_h);
    cudaGetSymbolAddress((void**)&wqh,  g_wq_h); cudaGetSymbolAddress((void**)&wql, g_wq_l);
    cudaGetSymbolAddress((void**)&wkvh, g_wkv_h);cudaGetSymbolAddress((void**)&wkvl,g_wkv_l);
    cudaGetSymbolAddress((void**)&winh, g_win_h);cudaGetSymbolAddress((void**)&winl,g_win_l);
    cudaGetSymbolAddress((void**)&woh,  g_wo_h); cudaGetSymbolAddress((void**)&wol, g_wo_l);
    cudaGetSymbolAddress((void**)&w1h,  g_w1_h);
    cudaGetSymbolAddress((void**)&w2h,  g_w2_h);

    cudaFuncSetAttribute(k_gemm_mma<3>, cudaFuncAttributeMaxDynamicSharedMemorySize, 3*STG);
    cudaFuncSetAttribute(k_gemm_mma<1>, cudaFuncAttributeMaxDynamicSharedMemorySize, 3*STG);
    const int GS = 3*STG;   // 184320

    // weight conversions (lo plane only where needed)
    k_cvt<<<(CC*CC)/1024,   256>>>(q_conv_w,  wqh,  wql,  CC*CC);
    k_cvt<<<(2*CC*CC)/1024, 256>>>(kv_conv_w, wkvh, wkvl, 2*CC*CC);
    k_cvt<<<(3*CC*CC)/1024, 256>>>(in_proj_w, winh, winl, 3*CC*CC);
    k_cvt<<<(CC*CC)/1024,   256>>>(out_proj_w,woh,  wol,  CC*CC);
    k_cvt<<<(MM*CC)/1024,   256>>>(w1,        w1h,  nullptr, MM*CC);
    k_cvt<<<(CC*MM)/1024,   256>>>(w2,        w2h,  nullptr, CC*MM);

    dim3 tgrid(LL/32, CC/32, BB), tblk(32, 8);
    k_transpose_in<<<tgrid, tblk>>>(x, xt, xth, xtl);

    // Q / KV projections (fp16 3-product split: near-fp32 exact)
    k_gemm_mma<3><<<dim3(CC/256,   BLROWS/128), 512, GS>>>(xth, xtl, wqh,  wql,  q_conv_b,  q,  CC,   CC);
    k_gemm_mma<3><<<dim3(2*CC/256, BLROWS/128), 512, GS>>>(xth, xtl, wkvh, wkvl, kv_conv_b, kv, 2*CC, CC);

    // LayerNorms (+l2n for Q,K)
    k_ln512<<<BLROWS/8, 256>>>(q,       CC,   q,  q_ln_g, q_ln_b, 1, nullptr, nullptr, qh, ql);
    k_ln512<<<BLROWS/8, 256>>>(kv,      2*CC, kn, k_ln_g, k_ln_b, 1, nullptr, nullptr, nullptr, nullptr);
    k_ln512<<<BLROWS/8, 256>>>(kv + CC, 2*CC, vt, v_ln_g, v_ln_b, 0, nullptr, nullptr, nullptr, nullptr);

    // probe, score, top-k, gather
    k_probe_partial<<<dim3(BB, 32), CC>>>(q, pp);
    k_probe_reduce<<<BB, CC>>>(pp, probe);
    k_score<<<(BB*LL*32)/256, 256>>>(kn, probe, score);
    k_topk<<<BB*HH, 512>>>(score, idx);
    k_gather<<<BB*TK, CC>>>(kn, vt, idx, kch, kcl, vch, vcl);

    // in_proj (3-product)
    k_gemm_mma<3><<<dim3(CC/256, BLROWS/128),  512, GS>>>(qh,  ql,  winh,           winl,           in_proj_b,        qp, CC, CC);
    k_gemm_mma<3><<<dim3(CC/256, (BB*TK)/128), 512, GS>>>(kch, kcl, winh + CC*CC,   winl + CC*CC,   in_proj_b + CC,   kp, CC, CC);
    k_gemm_mma<3><<<dim3(CC/256, (BB*TK)/128), 512, GS>>>(vch, vcl, winh + 2*CC*CC, winl + 2*CC*CC, in_proj_b + 2*CC, vp, CC, CC);

    // attention (257 keys: 256 selected + bias key) -> fp16 hi/lo
    k_attn<<<dim3(LL/64, BB*HH), 256>>>(qp, kp, vp, bias_k, bias_v, aoh, aol);

    // out_proj (3-product) -> h2(temp), attn LN * gamma + x residual -> a (+ hi only)
    k_gemm_mma<3><<<dim3(CC/256, BLROWS/128), 512, GS>>>(aoh, aol, woh, wol, out_proj_b, h2, CC, CC);
    k_ln512<<<BLROWS/8, 256>>>(h2, CC, a, attn_ln_g, attn_ln_b, 2, gamma, xt, ah, nullptr);

    // FFN (single-product fp16 — 61% of base FLOPs at 1/3 cost)
    k_gemm_mma<1><<<dim3(MM/256, BLROWS/128), 512, GS>>>(ah, nullptr, w1h, nullptr, b1, h1, MM, CC);
    k_ln2048<<<BLROWS/8, 256>>>(h1, n1_g, n1_b, h1h);
    k_gemm_mma<1><<<dim3(CC/256, BLROWS/128), 512, GS>>>(h1h, nullptr, w2h, nullptr, b2, h2, CC, MM);
    k_ln512<<<BLROWS/8, 256>>>(h2, CC, h2, n2_g, n2_b, 3, nullptr, nullptr, nullptr, nullptr);

    // out = transpose(h2 + a)
    k_add_transpose_out<<<tgrid, tblk>>>(h2, a, out);
}

// round 9
// speedup vs baseline: 1.3226x; 1.0953x over previous
#include <cuda_runtime.h>
#include <cuda_fp16.h>
#include <math.h>
#include <stdint.h>

// Problem constants
#define BB   8
#define CC   512
#define LL   4096
#define HH   8
#define TK   256
#define MM   2048
#define CHD  64
#define BLROWS (BB*LL)   // 32768

// ---------------- scratch (device globals; no allocation allowed) ----------
__device__ __align__(16) float g_xt  [(size_t)BB*LL*CC];
__device__ __align__(16) float g_q   [(size_t)BB*LL*CC];
__device__ __align__(16) float g_kv  [(size_t)BB*LL*2*CC];
__device__ __align__(16) float g_kn  [(size_t)BB*LL*CC];
__device__ __align__(16) float g_vt  [(size_t)BB*LL*CC];
__device__ __align__(16) float g_pp  [(size_t)BB*32*CC];
__device__ __align__(16) float g_probe[BB*CC];
__device__ __align__(16) float g_score[BB*HH*LL];
__device__ __align__(16) int   g_idx [BB*HH*TK];
__device__ __align__(16) float g_qp  [(size_t)BB*LL*CC];
__device__ __align__(16) float g_a   [(size_t)BB*LL*CC];
__device__ __align__(16) float g_h2  [(size_t)BB*LL*CC];
__device__ __align__(16) float g_h1  [(size_t)BB*LL*MM];

// fp16 activations
__device__ __align__(16) __half g_xt_h[(size_t)BB*LL*CC];
__device__ __align__(16) __half g_xt_l[(size_t)BB*LL*CC];   // lo plane: protects top-k path
__device__ __align__(16) __half g_q_h [(size_t)BB*LL*CC];
__device__ __align__(16) __half g_kc_h[(size_t)BB*TK*CC];
__device__ __align__(16) __half g_vc_h[(size_t)BB*TK*CC];
__device__ __align__(16) __half g_kp_h[(size_t)BB*TK*CC];   // in_proj K output (fp16)
__device__ __align__(16) __half g_vp_h[(size_t)BB*TK*CC];   // in_proj V output (fp16)
__device__ __align__(16) __half g_ao_h[(size_t)BB*LL*CC];
__device__ __align__(16) __half g_a_h [(size_t)BB*LL*CC];
__device__ __align__(16) __half g_h1_h[(size_t)BB*LL*MM];

// fp16 hi/lo weights
__device__ __align__(16) __half g_wq_h [CC*CC],    g_wq_l [CC*CC];
__device__ __align__(16) __half g_wkv_h[2*CC*CC],  g_wkv_l[2*CC*CC];
__device__ __align__(16) __half g_win_h[3*CC*CC],  g_win_l[3*CC*CC];
__device__ __align__(16) __half g_wo_h [CC*CC],    g_wo_l [CC*CC];
__device__ __align__(16) __half g_w1_h [MM*CC];
__device__ __align__(16) __half g_w2_h [CC*MM];

// ================= helpers ===================================================
static __device__ __forceinline__ uint32_t smem_u32(const void* p) {
    uint32_t a;
    asm("{ .reg .u64 t; cvta.to.shared.u64 t, %1; cvt.u32.u64 %0, t; }"
        : "=r"(a) : "l"(p));
    return a;
}
static __device__ __forceinline__ void split_f16(float v, __half& h, __half& l) {
    h = __float2half(v);
    l = __float2half(v - __half2float(h));
}
static __device__ __forceinline__ void ldmA(uint32_t* r, uint32_t addr) {
    asm volatile("ldmatrix.sync.aligned.m8n8.x4.shared.b16 {%0,%1,%2,%3}, [%4];"
                 : "=r"(r[0]), "=r"(r[1]), "=r"(r[2]), "=r"(r[3]) : "r"(addr));
}
static __device__ __forceinline__ void ldmB4(uint32_t* r, uint32_t addr) {
    asm volatile("ldmatrix.sync.aligned.m8n8.x4.shared.b16 {%0,%1,%2,%3}, [%4];"
                 : "=r"(r[0]), "=r"(r[1]), "=r"(r[2]), "=r"(r[3]) : "r"(addr));
}
static __device__ __forceinline__ void mma16816(float* d, const uint32_t* a, const uint32_t* b) {
    asm volatile(
        "mma.sync.aligned.m16n8k16.row.col.f32.f16.f16.f32 "
        "{%0,%1,%2,%3}, {%4,%5,%6,%7}, {%8,%9}, {%0,%1,%2,%3};"
        : "+f"(d[0]), "+f"(d[1]), "+f"(d[2]), "+f"(d[3])
        : "r"(a[0]), "r"(a[1]), "r"(a[2]), "r"(a[3]), "r"(b[0]), "r"(b[1]));
}
static __device__ __forceinline__ void cpasync16(uint32_t saddr, const void* gaddr) {
    asm volatile("cp.async.cg.shared.global [%0], [%1], 16;"
                 :: "r"(saddr), "l"(gaddr) : "memory");
}

// ================= tensor-core GEMM via mma.sync ============================
// Y(row,col) = X(row,K) * W(col,K)^T + bias[col]
// CTA tile 128x256, BK=32, 512 threads = 16 warps (4M x 4N), warp tile 32x64.
// NPROD==3: D += Ah*Bh + Ah*Bl + Al*Bh  (near-fp32 exact; top-k-safe)
// NPROD==2: D += Ah*Bh + Ah*Bl          (A fp16-quantized, B near-exact)
// NPROD==1: D += Ah*Bh                  (plain fp16)
// OUTH: write __half output instead of fp32.
template<int NPROD, bool OUTH>
__global__ void __launch_bounds__(512, 1) k_gemm_mma(
    const __half* __restrict__ Ah, const __half* __restrict__ Al,
    const __half* __restrict__ Bh, const __half* __restrict__ Bl,
    const float* __restrict__ bias, void* __restrict__ Yv, int N, int K)
{
    constexpr uint32_t A_OFF  = 0;
    constexpr uint32_t AL_OFF = 10240;                      // NPROD==3 only
    constexpr uint32_t BH_OFF = (NPROD == 3) ? 20480u : 10240u;
    constexpr uint32_t BL_OFF = (NPROD == 3) ? 40960u : 30720u;
    constexpr uint32_t STGB   = (NPROD == 3) ? 61440u : (NPROD == 2) ? 51200u : 30720u;

    extern __shared__ __align__(128) char smem[];
    const uint32_t sb = smem_u32(smem);
    const int tid  = threadIdx.x;
    const int wid  = tid >> 5, lane = tid & 31;
    const int wm   = wid & 3;              // warp M 0..3 (32 rows)
    const int wn   = wid >> 2;             // warp N 0..3 (64 cols)
    const int bm = blockIdx.y << 7, bn = blockIdx.x << 8;

    const int nch = K >> 5;                // chunks of BK=32

    float acc[2][8][4];
    #pragma unroll
    for (int m = 0; m < 2; m++)
        #pragma unroll
        for (int n = 0; n < 8; n++)
            #pragma unroll
            for (int v = 0; v < 4; v++) acc[m][n][v] = 0.f;

    // ---- async load of one chunk into stage s ----
    auto load_chunk = [&](int ck, int s) {
        const int k0 = ck << 5;
        const uint32_t so = sb + s * STGB;
        if (NPROD == 3) {
            #pragma unroll
            for (int i = 0; i < 6; i++) {
                const int idx = tid + (i << 9);   // 0..3071 16B units
                const __half* src;
                int local; uint32_t dst; int rb;
                if (i < 1)      { src = Ah; local = idx;        dst = A_OFF;  rb = bm; }
                else if (i < 2) { src = Al; local = idx - 512;  dst = AL_OFF; rb = bm; }
                else if (i < 4) { src = Bh; local = idx - 1024; dst = BH_OFF; rb = bn; }
                else            { src = Bl; local = idx - 2048; dst = BL_OFF; rb = bn; }
                const int row = local >> 2, seg = local & 3;
                cpasync16(so + dst + row * 80 + (seg << 4),
                          src + (size_t)(rb + row) * K + k0 + (seg << 3));
            }
        } else if (NPROD == 2) {
            #pragma unroll
            for (int i = 0; i < 5; i++) {
                const int idx = tid + (i << 9);
                const __half* src;
                int local; uint32_t dst; int rb;
                if (i < 1)      { src = Ah; local = idx;        dst = A_OFF;  rb = bm; }
                else if (i < 3) { src = Bh; local = idx - 512;  dst = BH_OFF; rb = bn; }
                else            { src = Bl; local = idx - 1536; dst = BL_OFF; rb = bn; }
                const int row = local >> 2, seg = local & 3;
                cpasync16(so + dst + row * 80 + (seg << 4),
                          src + (size_t)(rb + row) * K + k0 + (seg << 3));
            }
        } else {
            #pragma unroll
            for (int i = 0; i < 3; i++) {
                const int idx = tid + (i << 9);
                const __half* src;
                int local; uint32_t dst; int rb;
                if (i < 1) { src = Ah; local = idx;       dst = A_OFF;  rb = bm; }
                else       { src = Bh; local = idx - 512; dst = BH_OFF; rb = bn; }
                const int row = local >> 2, seg = local & 3;
                cpasync16(so + dst + row * 80 + (seg << 4),
                          src + (size_t)(rb + row) * K + k0 + (seg << 3));
            }
        }
        asm volatile("cp.async.commit_group;" ::: "memory");
    };

    load_chunk(0, 0);
    load_chunk(1, 1);

    // ldmatrix lane offsets
    const uint32_t aRow = (lane & 7) + ((lane >> 3) & 1) * 8;
    const uint32_t aKof = (lane >> 4) * 8;
    const uint32_t bRow = (lane & 7) + ((lane >> 4) & 1) * 8;
    const uint32_t bKof = ((lane >> 3) & 1) * 8;

    for (int ck = 0; ck < nch; ck++) {
        if (ck + 2 < nch) {
            load_chunk(ck + 2, (ck + 2) % 3);
            asm volatile("cp.async.wait_group 2;" ::: "memory");
        } else if (ck + 1 < nch) {
            asm volatile("cp.async.wait_group 1;" ::: "memory");
        } else {
            asm volatile("cp.async.wait_group 0;" ::: "memory");
        }
        __syncthreads();

        const uint32_t so = sb + (ck % 3) * STGB;
        #pragma unroll
        for (int ks = 0; ks < 2; ks++) {
            uint32_t ah[2][4], al[2][4];
            #pragma unroll
            for (int mf = 0; mf < 2; mf++) {
                uint32_t row = wm * 32 + mf * 16 + aRow;
                uint32_t off = row * 80 + (aKof + ks * 16) * 2;
                ldmA(ah[mf], so + A_OFF + off);
                if (NPROD == 3) ldmA(al[mf], so + AL_OFF + off);
            }
            #pragma unroll
            for (int ntp = 0; ntp < 4; ntp++) {        // pairs of n-tiles
                uint32_t row = wn * 64 + ntp * 16 + bRow;
                uint32_t off = row * 80 + (bKof + ks * 16) * 2;
                uint32_t bh[4], bl[4];
                ldmB4(bh, so + BH_OFF + off);
                if (NPROD >= 2) ldmB4(bl, so + BL_OFF + off);
                #pragma unroll
                for (int sub = 0; sub < 2; sub++) {
                    const int nt = ntp * 2 + sub;
                    #pragma unroll
                    for (int mf = 0; mf < 2; mf++) {
                        mma16816(acc[mf][nt], ah[mf], bh + 2*sub);
                        if (NPROD >= 2) mma16816(acc[mf][nt], ah[mf], bl + 2*sub);
                        if (NPROD == 3) mma16816(acc[mf][nt], al[mf], bh + 2*sub);
                    }
                }
            }
        }
        __syncthreads();
    }

    // ---- epilogue: bias add, fp32 or fp16 stores ----
    const int r  = lane >> 2;
    const int c2 = (lane & 3) << 1;
    #pragma unroll
    for (int mf = 0; mf < 2; mf++) {
        const int gm = bm + wm * 32 + mf * 16;
        #pragma unroll
        for (int nt = 0; nt < 8; nt++) {
            const int gn = bn + wn * 64 + nt * 8 + c2;
            float bx = bias[gn], by = bias[gn + 1];
            float o00 = acc[mf][nt][0] + bx, o01 = acc[mf][nt][1] + by;
            float o10 = acc[mf][nt][2] + bx, o11 = acc[mf][nt][3] + by;
            if (OUTH) {
                __half* Yh = (__half*)Yv;
                *(__half2*)(Yh + (size_t)(gm + r) * N + gn)     = __floats2half2_rn(o00, o01);
                *(__half2*)(Yh + (size_t)(gm + r + 8) * N + gn) = __floats2half2_rn(o10, o11);
            } else {
                float* Yf = (float*)Yv;
                *(float2*)(Yf + (size_t)(gm + r) * N + gn)     = make_float2(o00, o01);
                *(float2*)(Yf + (size_t)(gm + r + 8) * N + gn) = make_float2(o10, o11);
            }
        }
    }
}

// ---------------- weight fp32 -> fp16 hi/lo ---------------------------------
__global__ void k_cvt(const float* __restrict__ x, __half* __restrict__ h,
                      __half* __restrict__ l, int n) {
    int i = (blockIdx.x * 256 + threadIdx.x) * 4;
    if (i >= n) return;
    float4 v = *(const float4*)(x + i);
    __half hh, ll;
    split_f16(v.x, hh, ll); h[i+0] = hh; if (l) l[i+0] = ll;
    split_f16(v.y, hh, ll); h[i+1] = hh; if (l) l[i+1] = ll;
    split_f16(v.z, hh, ll); h[i+2] = hh; if (l) l[i+2] = ll;
    split_f16(v.w, hh, ll); h[i+3] = hh; if (l) l[i+3] = ll;
}

// ---------------- transpose (B,C,L) -> (B,L,C), fp32 + fp16 hi/lo ----------
__global__ void k_transpose_in(const float* __restrict__ X, float* __restrict__ Y,
                               __half* __restrict__ YH, __half* __restrict__ YL) {
    __shared__ float tile[32][33];
    int b  = blockIdx.z;
    int l0 = blockIdx.x << 5, c0 = blockIdx.y << 5;
    int tx = threadIdx.x, ty = threadIdx.y;
    const float* Xb = X + (size_t)b*CC*LL;
    #pragma unroll
    for (int i = ty; i < 32; i += 8)
        tile[i][tx] = Xb[(size_t)(c0+i)*LL + l0 + tx];
    __syncthreads();
    size_t base = (size_t)b*LL*CC;
    #pragma unroll
    for (int i = ty; i < 32; i += 8) {
        float v = tile[tx][i];
        size_t o = base + (size_t)(l0+i)*CC + c0 + tx;
        Y[o] = v;
        __half hh, ll; split_f16(v, hh, ll);
        YH[o] = hh; YL[o] = ll;
    }
}

// ---------------- out = transpose(H + A), (B,L,C) -> (B,C,L) ---------------
__global__ void k_add_transpose_out(const float* __restrict__ Hh, const float* __restrict__ A,
                                    float* __restrict__ OUT) {
    __shared__ float tile[32][33];
    int b  = blockIdx.z;
    int l0 = blockIdx.x << 5, c0 = blockIdx.y << 5;
    int tx = threadIdx.x, ty = threadIdx.y;
    const float* Hb = Hh + (size_t)b*LL*CC;
    const float* Ab = A  + (size_t)b*LL*CC;
    #pragma unroll
    for (int i = ty; i < 32; i += 8) {
        size_t o = (size_t)(l0+i)*CC + c0 + tx;
        tile[i][tx] = Hb[o] + Ab[o];
    }
    __syncthreads();
    float* Ob = OUT + (size_t)b*CC*LL;
    #pragma unroll
    for (int i = ty; i < 32; i += 8)
        Ob[(size_t)(c0+i)*LL + l0 + tx] = tile[tx][i];
}

// ---------------- warp-per-row LayerNorm, Wd=512, fused epilogues -----------
// mode 0: plain LN ; 1: LN + per-64-chunk l2n ; 2: LN*gamma + resid ; 3: relu
__global__ void k_ln512(const float* __restrict__ in, int ld_in,
                        float* __restrict__ out,
                        const float* __restrict__ gam, const float* __restrict__ bet,
                        int mode, const float* __restrict__ gamma_p,
                        const float* __restrict__ resid,
                        __half* __restrict__ oh) {
    const int lane = threadIdx.x & 31;
    const int row  = blockIdx.x * 8 + (threadIdx.x >> 5);
    const float* xr = in + (size_t)row * ld_in + lane * 16;

    float v[16];
    float s = 0.f, s2 = 0.f;
    #pragma unroll
    for (int j = 0; j < 16; j += 4) {
        float4 t = *(const float4*)(xr + j);
        v[j]=t.x; v[j+1]=t.y; v[j+2]=t.z; v[j+3]=t.w;
        s += t.x+t.y+t.z+t.w;
        s2 += t.x*t.x+t.y*t.y+t.z*t.z+t.w*t.w;
    }
    #pragma unroll
    for (int o = 16; o > 0; o >>= 1) {
        s  += __shfl_xor_sync(0xffffffffu, s,  o);
        s2 += __shfl_xor_sync(0xffffffffu, s2, o);
    }
    const float mu = s * (1.f/512.f);
    const float rstd = rsqrtf(s2 * (1.f/512.f) - mu*mu + 1e-5f);

    float y[16];
    const int cb = lane * 16;
    #pragma unroll
    for (int i = 0; i < 16; i++)
        y[i] = (v[i] - mu) * rstd * gam[cb + i] + bet[cb + i];

    if (mode == 1) {           // l2n over 64-ch chunk = 4 adjacent lanes
        float qq = 0.f;
        #pragma unroll
        for (int i = 0; i < 16; i++) qq += y[i]*y[i];
        qq += __shfl_xor_sync(0xffffffffu, qq, 1);
        qq += __shfl_xor_sync(0xffffffffu, qq, 2);
        float sc = 1.f / fmaxf(sqrtf(qq), 1e-12f);
        #pragma unroll
        for (int i = 0; i < 16; i++) y[i] *= sc;
    } else if (mode == 2) {
        float gsc = gamma_p[0];
        const float* rr = resid + (size_t)row * 512 + cb;
        #pragma unroll
        for (int i = 0; i < 16; i++) y[i] = y[i]*gsc + rr[i];
    } else if (mode == 3) {
        #pragma unroll
        for (int i = 0; i < 16; i++) y[i] = fmaxf(y[i], 0.f);
    }
    size_t ob = (size_t)row * 512 + cb;
    if (out) {
        #pragma unroll
        for (int j = 0; j < 16; j += 4)
            *(float4*)(out + ob + j) = make_float4(y[j], y[j+1], y[j+2], y[j+3]);
    }
    if (oh) {
        __half2* dst = (__half2*)(oh + ob);
        #pragma unroll
        for (int j = 0; j < 16; j += 2)
            dst[j >> 1] = __floats2half2_rn(y[j], y[j+1]);
    }
}

// ---------------- warp-per-row LN+relu, Wd=2048, fp16 hi out only -----------
__global__ void k_ln2048(const float* __restrict__ in,
                         const float* __restrict__ gam, const float* __restrict__ bet,
                         __half* __restrict__ oh) {
    const int lane = threadIdx.x & 31;
    const int row  = blockIdx.x * 8 + (threadIdx.x >> 5);
    const float* xr = in + (size_t)row * 2048;

    float s = 0.f, s2 = 0.f;
    #pragma unroll
    for (int w = 0; w < 16; w++) {
        float4 t = *(const float4*)(xr + ((w*32 + lane) << 2));
        s  += t.x+t.y+t.z+t.w;
        s2 += t.x*t.x+t.y*t.y+t.z*t.z+t.w*t.w;
    }
    #pragma unroll
    for (int o = 16; o > 0; o >>= 1) {
        s  += __shfl_xor_sync(0xffffffffu, s,  o);
        s2 += __shfl_xor_sync(0xffffffffu, s2, o);
    }
    const float mu = s * (1.f/2048.f);
    const float rstd = rsqrtf(s2 * (1.f/2048.f) - mu*mu + 1e-5f);

    #pragma unroll
    for (int w = 0; w < 16; w++) {
        const int e = (w*32 + lane) << 2;
        float4 t = *(const float4*)(xr + e);
        float4 g = *(const float4*)(gam + e);
        float4 bb = *(const float4*)(bet + e);
        float y0 = fmaxf((t.x-mu)*rstd*g.x + bb.x, 0.f);
        float y1 = fmaxf((t.y-mu)*rstd*g.y + bb.y, 0.f);
        float y2 = fmaxf((t.z-mu)*rstd*g.z + bb.z, 0.f);
        float y3 = fmaxf((t.w-mu)*rstd*g.w + bb.w, 0.f);
        size_t ob = (size_t)row * 2048 + e;
        __half2* dst = (__half2*)(oh + ob);
        dst[0] = __floats2half2_rn(y0, y1);
        dst[1] = __floats2half2_rn(y2, y3);
    }
}

// ---------------- q_probe = sum over L of QN --------------------------------
__global__ void k_probe_partial(const float* __restrict__ QN, float* __restrict__ part) {
    int b = blockIdx.x, ch = blockIdx.y;
    int c = threadIdx.x;
    const int CHUNK = LL / 32;
    const float* p = QN + ((size_t)b*LL + (size_t)ch*CHUNK)*CC + c;
    float s = 0.f;
    for (int i = 0; i < CHUNK; i++) s += p[(size_t)i*CC];
    part[((size_t)b*32 + ch)*CC + c] = s;
}
__global__ void k_probe_reduce(const float* __restrict__ part, float* __restrict__ probe) {
    int b = blockIdx.x; int c = threadIdx.x;
    float s = 0.f;
    for (int ch = 0; ch < 32; ch++) s += part[((size_t)b*32 + ch)*CC + c];
    probe[b*CC + c] = s;
}

// ---------------- score[b,h,l] = probe . (|k|+k) -----------------------------
__global__ void k_score(const float* __restrict__ KN, const float* __restrict__ probe,
                        float* __restrict__ score) {
    int gw   = (blockIdx.x * blockDim.x + threadIdx.x) >> 5;
    int lane = threadIdx.x & 31;
    if (gw >= BB*LL) return;
    int b = gw >> 12;
    int l = gw & (LL-1);
    const float* krow = KN + (size_t)gw*CC;
    const float* pr   = probe + b*CC;
    int c0 = lane << 4;
    float s = 0.f;
    #pragma unroll
    for (int j = 0; j < 16; j += 4) {
        float4 k4 = *(const float4*)(krow + c0 + j);
        float4 p4 = *(const float4*)(pr   + c0 + j);
        s += p4.x*(fabsf(k4.x)+k4.x) + p4.y*(fabsf(k4.y)+k4.y)
           + p4.z*(fabsf(k4.z)+k4.z) + p4.w*(fabsf(k4.w)+k4.w);
    }
    s += __shfl_xor_sync(0xffffffffu, s, 1);
    s += __shfl_xor_sync(0xffffffffu, s, 2);
    if ((lane & 3) == 0) {
        int h = lane >> 2;
        score[((size_t)(b*HH + h))*LL + l] = s;
    }
}

// ---------------- exact top-k via in-smem bitonic sort -----------------------
__global__ void k_topk(const float* __restrict__ score, int* __restrict__ idx) {
    __shared__ unsigned long long keys[LL];
    int bh = blockIdx.x;
    const float* s = score + (size_t)bh*LL;
    for (int i = threadIdx.x; i < LL; i += blockDim.x) {
        unsigned u = __float_as_uint(s[i]);
        u = (u & 0x80000000u) ? ~u : (u | 0x80000000u);
        keys[i] = ((unsigned long long)u << 32) | (unsigned)(LL-1-i);
    }
    __syncthreads();
    for (int k = 2; k <= LL; k <<= 1) {
        for (int j = k >> 1; j > 0; j >>= 1) {
            for (int i = threadIdx.x; i < LL; i += blockDim.x) {
                int ixj = i ^ j;
                if (ixj > i) {
                    unsigned long long a = keys[i], c = keys[ixj];
                    bool desc = (i & k) == 0;
                    if (desc ? (a < c) : (a > c)) { keys[i] = c; keys[ixj] = a; }
                }
            }
            __syncthreads();
        }
    }
    for (int t = threadIdx.x; t < TK; t += blockDim.x)
        idx[bh*TK + t] = (LL-1) - (int)(unsigned)(keys[t] & 0xffffffffu);
}

// ---------------- gather selected K/V rows per head -> fp16 hi ---------------
__global__ void k_gather(const float* __restrict__ KN, const float* __restrict__ VT,
                         const int* __restrict__ idx,
                         __half* __restrict__ KCH, __half* __restrict__ VCH) {
    int bt = blockIdx.x;
    int b = bt / TK, t = bt % TK;
    int c = threadIdx.x;
    int h = c >> 6;
    int l = idx[(b*HH + h)*TK + t];
    size_t src = ((size_t)b*LL + l)*CC + c;
    size_t dst = (size_t)bt*CC + c;
    KCH[dst] = __float2half(KN[src]);
    VCH[dst] = __float2half(VT[src]);
}

// ---------------- attention: per (b,h,64-query tile), online softmax ---------
// K/V inputs now fp16 (halved traffic); converted to fp32 in smem.
__global__ void k_attn(const float* __restrict__ QP, const __half* __restrict__ KP,
                       const __half* __restrict__ VP, const float* __restrict__ bk,
                       const float* __restrict__ bv,
                       __half* __restrict__ AOH) {
    __shared__ float Ks[64][64];
    __shared__ float Vs[64][64];
    int bh = blockIdx.y;
    int b = bh >> 3, h = bh & 7;
    int l0 = blockIdx.x << 6;
    int tid = threadIdx.x;
    int g = tid >> 2;
    int r = tid & 3;
    int l = l0 + g;
    const int cbase = h*CHD + r*16;

    float q[16];
    const float* qrow = QP + ((size_t)b*LL + l)*CC + cbase;
    #pragma unroll
    for (int i = 0; i < 16; i++) q[i] = qrow[i];

    float acc[16];
    #pragma unroll
    for (int i = 0; i < 16; i++) acc[i] = 0.f;
    float m = -1e30f, denom = 0.f;

    for (int kc0 = 0; kc0 < TK; kc0 += 64) {
        for (int i = tid; i < 64*32; i += 256) {          // 2 half2 per elem pair
            int rowk = i >> 5, cc = (i & 31) << 1;
            size_t src = ((size_t)b*TK + kc0 + rowk)*CC + h*CHD + cc;
            float2 kf = __half22float2(*(const __half2*)(KP + src));
            float2 vf = __half22float2(*(const __half2*)(VP + src));
            Ks[rowk][cc] = kf.x; Ks[rowk][cc+1] = kf.y;
            Vs[rowk][cc] = vf.x; Vs[rowk][cc+1] = vf.y;
        }
        __syncthreads();
        for (int j = 0; j < 64; j++) {
            float part = 0.f;
            #pragma unroll
            for (int i = 0; i < 16; i++) part += q[i]*Ks[j][r*16 + i];
            part += __shfl_xor_sync(0xffffffffu, part, 1);
            part += __shfl_xor_sync(0xffffffffu, part, 2);
            float sc = part * 0.125f;
            if (sc > m) {
                float corr = __expf(m - sc);
                denom *= corr;
                #pragma unroll
                for (int i = 0; i < 16; i++) acc[i] *= corr;
                m = sc;
            }
            float p = __expf(sc - m);
            denom += p;
            #pragma unroll
            for (int i = 0; i < 16; i++) acc[i] += p*Vs[j][r*16 + i];
        }
        __syncthreads();
    }
    {
        float part = 0.f;
        #pragma unroll
        for (int i = 0; i < 16; i++) part += q[i]*bk[cbase + i];
        part += __shfl_xor_sync(0xffffffffu, part, 1);
        part += __shfl_xor_sync(0xffffffffu, part, 2);
        float sc = part * 0.125f;
        if (sc > m) {
            float corr = __expf(m - sc);
            denom *= corr;
            #pragma unroll
            for (int i = 0; i < 16; i++) acc[i] *= corr;
            m = sc;
        }
        float p = __expf(sc - m);
        denom += p;
        #pragma unroll
        for (int i = 0; i < 16; i++) acc[i] += p*bv[cbase + i];
    }
    float inv = 1.f / denom;
    size_t obase = ((size_t)b*LL + l)*CC + cbase;
    __half2* dst = (__half2*)(AOH + obase);
    #pragma unroll
    for (int i = 0; i < 16; i += 2)
        dst[i >> 1] = __floats2half2_rn(acc[i]*inv, acc[i+1]*inv);
}

// ---------------------------- launcher ---------------------------------------
extern "C" void kernel_launch(void* const* d_in, const int* in_sizes, int n_in,
                              void* d_out, int out_size) {
    const float* x         = (const float*)d_in[0];
    const float* q_conv_w  = (const float*)d_in[1];
    const float* q_conv_b  = (const float*)d_in[2];
    const float* q_ln_g    = (const float*)d_in[3];
    const float* q_ln_b    = (const float*)d_in[4];
    const float* kv_conv_w = (const float*)d_in[5];
    const float* kv_conv_b = (const float*)d_in[6];
    const float* k_ln_g    = (const float*)d_in[7];
    const float* k_ln_b    = (const float*)d_in[8];
    const float* v_ln_g    = (const float*)d_in[9];
    const float* v_ln_b    = (const float*)d_in[10];
    const float* in_proj_w = (const float*)d_in[11];
    const float* in_proj_b = (const float*)d_in[12];
    const float* bias_k    = (const float*)d_in[13];
    const float* bias_v    = (const float*)d_in[14];
    const float* out_proj_w= (const float*)d_in[15];
    const float* out_proj_b= (const float*)d_in[16];
    const float* attn_ln_g = (const float*)d_in[17];
    const float* attn_ln_b = (const float*)d_in[18];
    const float* gamma     = (const float*)d_in[19];
    const float* w1        = (const float*)d_in[20];
    const float* b1        = (const float*)d_in[21];
    const float* n1_g      = (const float*)d_in[22];
    const float* n1_b      = (const float*)d_in[23];
    const float* w2        = (const float*)d_in[24];
    const float* b2        = (const float*)d_in[25];
    const float* n2_g      = (const float*)d_in[26];
    const float* n2_b      = (const float*)d_in[27];
    float* out = (float*)d_out;

    float *xt, *q, *kv, *kn, *vt, *pp, *probe, *score, *qp, *a, *h1, *h2;
    int* idx;
    __half *xth,*xtl,*qh,*kch,*vch,*kph,*vph,*aoh,*ah,*h1h;
    __half *wqh,*wql,*wkvh,*wkvl,*winh,*winl,*woh,*wol,*w1h,*w2h;

    cudaGetSymbolAddress((void**)&xt,   g_xt);
    cudaGetSymbolAddress((void**)&q,    g_q);
    cudaGetSymbolAddress((void**)&kv,   g_kv);
    cudaGetSymbolAddress((void**)&kn,   g_kn);
    cudaGetSymbolAddress((void**)&vt,   g_vt);
    cudaGetSymbolAddress((void**)&pp,   g_pp);
    cudaGetSymbolAddress((void**)&probe,g_probe);
    cudaGetSymbolAddress((void**)&score,g_score);
    cudaGetSymbolAddress((void**)&idx,  g_idx);
    cudaGetSymbolAddress((void**)&qp,   g_qp);
    cudaGetSymbolAddress((void**)&a,    g_a);
    cudaGetSymbolAddress((void**)&h1,   g_h1);
    cudaGetSymbolAddress((void**)&h2,   g_h2);
    cudaGetSymbolAddress((void**)&xth,  g_xt_h);
    cudaGetSymbolAddress((void**)&xtl,  g_xt_l);
    cudaGetSymbolAddress((void**)&qh,   g_q_h);
    cudaGetSymbolAddress((void**)&kch,  g_kc_h);
    cudaGetSymbolAddress((void**)&vch,  g_vc_h);
    cudaGetSymbolAddress((void**)&kph,  g_kp_h);
    cudaGetSymbolAddress((void**)&vph,  g_vp_h);
    cudaGetSymbolAddress((void**)&aoh,  g_ao_h);
    cudaGetSymbolAddress((void**)&ah,   g_a_h);
    cudaGetSymbolAddress((void**)&h1h,  g_h1_h);
    cudaGetSymbolAddress((void**)&wqh,  g_wq_h); cudaGetSymbolAddress((void**)&wql, g_wq_l);
    cudaGetSymbolAddress((void**)&wkvh, g_wkv_h);cudaGetSymbolAddress((void**)&wkvl,g_wkv_l);
    cudaGetSymbolAddress((void**)&winh, g_win_h);cudaGetSymbolAddress((void**)&winl,g_win_l);
    cudaGetSymbolAddress((void**)&woh,  g_wo_h); cudaGetSymbolAddress((void**)&wol, g_wo_l);
    cudaGetSymbolAddress((void**)&w1h,  g_w1_h);
    cudaGetSymbolAddress((void**)&w2h,  g_w2_h);

    cudaFuncSetAttribute((const void*)k_gemm_mma<3,false>, cudaFuncAttributeMaxDynamicSharedMemorySize, 3*61440);
    cudaFuncSetAttribute((const void*)k_gemm_mma<2,false>, cudaFuncAttributeMaxDynamicSharedMemorySize, 3*51200);
    cudaFuncSetAttribute((const void*)k_gemm_mma<2,true>,  cudaFuncAttributeMaxDynamicSharedMemorySize, 3*51200);
    cudaFuncSetAttribute((const void*)k_gemm_mma<1,false>, cudaFuncAttributeMaxDynamicSharedMemorySize, 3*30720);
    const int GS3 = 3*61440;   // 184320
    const int GS2 = 3*51200;   // 153600
    const int GS1 = 3*30720;   // 92160

    // weight conversions
    k_cvt<<<(CC*CC)/1024,   256>>>(q_conv_w,  wqh,  wql,  CC*CC);
    k_cvt<<<(2*CC*CC)/1024, 256>>>(kv_conv_w, wkvh, wkvl, 2*CC*CC);
    k_cvt<<<(3*CC*CC)/1024, 256>>>(in_proj_w, winh, winl, 3*CC*CC);
    k_cvt<<<(CC*CC)/1024,   256>>>(out_proj_w,woh,  wol,  CC*CC);

    dim3 tgrid(LL/32, CC/32, BB), tblk(32, 8);
    k_transpose_in<<<tgrid, tblk>>>(x, xt, xth, xtl);

    // Q / KV projections (3-product: near-exact — protects top-k selection)
    k_gemm_mma<3,false><<<dim3(CC/256,   BLROWS/128), 512, GS3>>>(xth, xtl, wqh,  wql,  q_conv_b,  q,  CC,   CC);

    k_cvt<<<(MM*CC)/1024, 256>>>(w1, w1h, nullptr, MM*CC);
    k_cvt<<<(CC*MM)/1024, 256>>>(w2, w2h, nullptr, CC*MM);

    k_gemm_mma<3,false><<<dim3(2*CC/256, BLROWS/128), 512, GS3>>>(xth, xtl, wkvh, wkvl, kv_conv_b, kv, 2*CC, CC);

    // LayerNorms (+l2n for Q,K)
    k_ln512<<<BLROWS/8, 256>>>(q,       CC,   q,  q_ln_g, q_ln_b, 1, nullptr, nullptr, qh);
    k_ln512<<<BLROWS/8, 256>>>(kv,      2*CC, kn, k_ln_g, k_ln_b, 1, nullptr, nullptr, nullptr);
    k_ln512<<<BLROWS/8, 256>>>(kv + CC, 2*CC, vt, v_ln_g, v_ln_b, 0, nullptr, nullptr, nullptr);

    // probe, score, top-k, gather
    k_probe_partial<<<dim3(BB, 32), CC>>>(q, pp);
    k_probe_reduce<<<BB, CC>>>(pp, probe);
    k_score<<<(BB*LL*32)/256, 256>>>(kn, probe, score);
    k_topk<<<BB*HH, 512>>>(score, idx);
    k_gather<<<BB*TK, CC>>>(kn, vt, idx, kch, vch);

    // in_proj (2-product; after selection — smooth error path)
    k_gemm_mma<2,false><<<dim3(CC/256, BLROWS/128),  512, GS2>>>(qh,  nullptr, winh,           winl,           in_proj_b,        qp,  CC, CC);
    k_gemm_mma<2,true ><<<dim3(CC/256, (BB*TK)/128), 512, GS2>>>(kch, nullptr, winh + CC*CC,   winl + CC*CC,   in_proj_b + CC,   kph, CC, CC);
    k_gemm_mma<2,true ><<<dim3(CC/256, (BB*TK)/128), 512, GS2>>>(vch, nullptr, winh + 2*CC*CC, winl + 2*CC*CC, in_proj_b + 2*CC, vph, CC, CC);

    // attention (257 keys: 256 selected + bias key), K/V fp16 -> fp16 hi out
    k_attn<<<dim3(LL/64, BB*HH), 256>>>(qp, kph, vph, bias_k, bias_v, aoh);

    // out_proj (2-product) -> h2(temp), attn LN * gamma + x residual -> a (+ hi)
    k_gemm_mma<2,false><<<dim3(CC/256, BLROWS/128), 512, GS2>>>(aoh, nullptr, woh, wol, out_proj_b, h2, CC, CC);
    k_ln512<<<BLROWS/8, 256>>>(h2, CC, a, attn_ln_g, attn_ln_b, 2, gamma, xt, ah);

    // FFN (single-product fp16)
    k_gemm_mma<1,false><<<dim3(MM/256, BLROWS/128), 512, GS1>>>(ah, nullptr, w1h, nullptr, b1, h1, MM, CC);
    k_ln2048<<<BLROWS/8, 256>>>(h1, n1_g, n1_b, h1h);
    k_gemm_mma<1,false><<<dim3(CC/256, BLROWS/128), 512, GS1>>>(h1h, nullptr, w2h, nullptr, b2, h2, CC, MM);
    k_ln512<<<BLROWS/8, 256>>>(h2, CC, h2, n2_g, n2_b, 3, nullptr, nullptr, nullptr);

    // out = transpose(h2 + a)
    k_add_transpose_out<<<tgrid, tblk>>>(h2, a, out);
}